// round 14
// baseline (speedup 1.0000x reference)
#include <cuda_runtime.h>
#include <cuda_fp16.h>
#include <cuda_fp8.h>
#include <math.h>
#include <stdint.h>

// ---------------- problem dims ----------------
#define NB    4096
#define NIN   8192
#define NEMB  1024
#define NK    4096
#define NCD   256
#define NFLAT 16384
#define OUT_PERP_OFF ((size_t)1 + (size_t)NB * (size_t)NIN)

#define EPI_BN_RELU 0
#define EPI_BIAS    1
#define EPI_RES     2
#define EPI_SIG     3

#define QSCALE     4096.0f
#define QSCALE_INV 0.000244140625f

// ---------------- scratch (device globals) ----------------
__device__ __half  g_xh [(size_t)NB * NIN];
__device__ __half  g_w1t[(size_t)NIN * NEMB];
__device__ __half  g_wts[(size_t)3 * NEMB * NEMB];    // W2, rb0, rb1 (fp16, [n][k])
__device__ uint8_t g_wq [(size_t)3 * NEMB * NEMB];    // rb2, rb3, rb4 (e4m3, [n][k])
__device__ uint8_t g_wqd[(size_t)NIN * NEMB];         // decW (e4m3, [n][k])
__device__ __half  g_cbh[(size_t)NK * NCD];
__device__ __half  g_ha [(size_t)NB * NEMB];
__device__ __half  g_har[(size_t)NB * NEMB];
__device__ __half  g_hb [(size_t)NB * NEMB];
__device__ __half  g_z  [(size_t)NB * NEMB];
__device__ uint8_t g_q1 [(size_t)NB * NEMB];
__device__ uint8_t g_q2 [(size_t)NB * NEMB];
__device__ float   g_cnorm[NK];
__device__ int     g_cnt[NK];
__device__ float   g_losspart[NFLAT / 128];

// ---------------- helpers ----------------
__device__ __forceinline__ void cp16(uint32_t dst, const void* src) {
    asm volatile("cp.async.cg.shared.global [%0], [%1], 16;" :: "r"(dst), "l"(src));
}
__device__ __forceinline__ void cp_commit() {
    asm volatile("cp.async.commit_group;");
}
template<int N>
__device__ __forceinline__ void cp_wait() {
    asm volatile("cp.async.wait_group %0;" :: "n"(N));
}
__device__ __forceinline__ void mma16(float* c, const uint32_t* a, const uint32_t* b) {
    asm volatile(
        "mma.sync.aligned.m16n8k16.row.col.f32.f16.f16.f32 "
        "{%0,%1,%2,%3},{%4,%5,%6,%7},{%8,%9},{%0,%1,%2,%3};"
        : "+f"(c[0]), "+f"(c[1]), "+f"(c[2]), "+f"(c[3])
        : "r"(a[0]), "r"(a[1]), "r"(a[2]), "r"(a[3]), "r"(b[0]), "r"(b[1]));
}
__device__ __forceinline__ void mmaq(float* c, const uint32_t* a, const uint32_t* b) {
    asm volatile(
        "mma.sync.aligned.m16n8k32.row.col.f32.e4m3.e4m3.f32 "
        "{%0,%1,%2,%3},{%4,%5,%6,%7},{%8,%9},{%0,%1,%2,%3};"
        : "+f"(c[0]), "+f"(c[1]), "+f"(c[2]), "+f"(c[3])
        : "r"(a[0]), "r"(a[1]), "r"(a[2]), "r"(a[3]), "r"(b[0]), "r"(b[1]));
}
__device__ __forceinline__ void ldsm4(uint32_t& r0, uint32_t& r1, uint32_t& r2, uint32_t& r3,
                                      uint32_t addr) {
    asm volatile("ldmatrix.sync.aligned.m8n8.x4.shared.b16 {%0,%1,%2,%3}, [%4];"
                 : "=r"(r0), "=r"(r1), "=r"(r2), "=r"(r3) : "r"(addr));
}
__device__ __forceinline__ uint16_t pack_q2(float lo, float hi) {
    uint16_t r;
    asm("cvt.rn.satfinite.e4m3x2.f32 %0, %1, %2;" : "=h"(r) : "f"(hi), "f"(lo));
    return r;
}
__device__ __forceinline__ uint32_t relu_h2(uint32_t v) {
    __half2 h = *(__half2*)&v;
    h = __hmax2(h, __float2half2_rn(0.f));
    return *(uint32_t*)&h;
}

// ================= fp16 tensor-core GEMM (256 thr, 3-stage, ldmatrix, frag double-buffer) =================
#define HBK   64
#define HA_STR 72
#define HAS   (128 * HA_STR)
#define HBS   (256 * HA_STR)
#define SMEM_H16 (3 * (HAS * 2 + HBS * 2))

template<int EPI, bool RELUA>
__global__ void __launch_bounds__(256, 1)
gemm_h(const __half* __restrict__ Ain, const __half* __restrict__ WT,
       const float* __restrict__ bias,
       const float* __restrict__ gamma, const float* __restrict__ beta,
       const float* __restrict__ mean,  const float* __restrict__ var,
       const __half* __restrict__ res,
       __half* __restrict__ out0,
       int M, int N, int K)
{
    extern __shared__ char smem[];
    const int ASTG = HAS * 2;
    const int BSTG = HBS * 2;
    __half* Bh = (__half*)(smem + 3 * ASTG);
    const uint32_t s_a = (uint32_t)__cvta_generic_to_shared(smem);
    const uint32_t s_b = (uint32_t)__cvta_generic_to_shared(Bh);

    const int tid  = threadIdx.x;
    const int lane = tid & 31;
    const int warp = tid >> 5;
    const int wm   = warp >> 2;
    const int wn   = warp & 3;
    const int row0 = blockIdx.y * 128;
    const int col0 = blockIdx.x * 256;
    const int l4   = lane >> 2;
    const int lm   = lane & 3;
    const int t8   = lane >> 3;
    const int jr   = lane & 7;

    uint32_t aBase[4], bBase[4];
#pragma unroll
    for (int mt = 0; mt < 4; mt++) {
        int r = wm * 64 + mt * 16 + ((t8 & 1) << 3) + jr;
        int c = (t8 >> 1) << 3;
        aBase[mt] = s_a + (uint32_t)(r * HA_STR + c) * 2;
    }
#pragma unroll
    for (int p = 0; p < 4; p++) {
        int r = wn * 64 + (2 * p + (t8 >> 1)) * 8 + jr;
        int c = (t8 & 1) << 3;
        bBase[p] = s_b + (uint32_t)(r * HA_STR + c) * 2;
    }

    float acc[4][8][4];
#pragma unroll
    for (int mt = 0; mt < 4; mt++)
#pragma unroll
        for (int nt = 0; nt < 8; nt++)
#pragma unroll
            for (int q = 0; q < 4; q++) acc[mt][nt][q] = 0.f;

    const int iters = K / HBK;

    auto loadA = [&](int s, int k0) {
#pragma unroll
        for (int i = 0; i < 4; i++) {
            int idx = i * 256 + tid;
            int r = idx >> 3, kc = (idx & 7) << 3;
            cp16(s_a + (uint32_t)(s * ASTG) + (uint32_t)(r * HA_STR + kc) * 2,
                 Ain + (size_t)(row0 + r) * K + k0 + kc);
        }
    };
    auto loadB = [&](int s, int k0) {
#pragma unroll
        for (int i = 0; i < 8; i++) {
            int idx = i * 256 + tid;
            int n = idx >> 3, kc = (idx & 7) << 3;
            cp16(s_b + (uint32_t)(s * BSTG) + (uint32_t)(n * HA_STR + kc) * 2,
                 WT + (size_t)(col0 + n) * K + k0 + kc);
        }
    };

    loadA(0, 0); loadB(0, 0); cp_commit();
    loadA(1, HBK); loadB(1, HBK); cp_commit();

    for (int it = 0; it < iters; it++) {
        if (it + 1 < iters) cp_wait<1>(); else cp_wait<0>();
        __syncthreads();
        if (it + 2 < iters) {
            int ps = (it + 2) % 3;
            loadA(ps, (it + 2) * HBK);
            loadB(ps, (it + 2) * HBK);
            cp_commit();
        }

        const int s = it % 3;
        const uint32_t aOff = (uint32_t)(s * ASTG);
        const uint32_t bOff = (uint32_t)(s * BSTG);

        uint32_t af[2][4][4], bf[2][8][2];
        auto ldfrag = [&](int buf, int kk) {
#pragma unroll
            for (int mt = 0; mt < 4; mt++) {
                ldsm4(af[buf][mt][0], af[buf][mt][1], af[buf][mt][2], af[buf][mt][3],
                      aBase[mt] + aOff + (uint32_t)kk * 2);
                if (RELUA) {
#pragma unroll
                    for (int i = 0; i < 4; i++) af[buf][mt][i] = relu_h2(af[buf][mt][i]);
                }
            }
#pragma unroll
            for (int p = 0; p < 4; p++)
                ldsm4(bf[buf][2 * p][0], bf[buf][2 * p][1],
                      bf[buf][2 * p + 1][0], bf[buf][2 * p + 1][1],
                      bBase[p] + bOff + (uint32_t)kk * 2);
        };

        ldfrag(0, 0);
#pragma unroll
        for (int ks = 0; ks < 4; ks++) {
            const int cur = ks & 1;
            if (ks < 3) ldfrag(cur ^ 1, (ks + 1) * 16);
#pragma unroll
            for (int mt = 0; mt < 4; mt++)
#pragma unroll
                for (int nt = 0; nt < 8; nt++)
                    mma16(acc[mt][nt], af[cur][mt], bf[cur][nt]);
        }
    }

    // ---- epilogue (single fp16 output) ----
#pragma unroll
    for (int nt = 0; nt < 8; nt++) {
        int c = col0 + wn * 64 + nt * 8 + (lm << 1);
        float b0 = bias[c], b1 = bias[c + 1];
        float g0 = 0.f, g1 = 0.f, be0 = 0.f, be1 = 0.f, m0 = 0.f, m1 = 0.f;
        if (EPI == EPI_BN_RELU || EPI == EPI_RES) {
            g0 = gamma[c]     * rsqrtf(var[c]     + 1e-5f);
            g1 = gamma[c + 1] * rsqrtf(var[c + 1] + 1e-5f);
            be0 = beta[c]; be1 = beta[c + 1];
            m0 = mean[c]; m1 = mean[c + 1];
        }
#pragma unroll
        for (int mt = 0; mt < 4; mt++) {
#pragma unroll
            for (int h = 0; h < 2; h++) {
                int r = row0 + wm * 64 + mt * 16 + l4 + h * 8;
                size_t off = (size_t)r * N + c;
                float x0 = acc[mt][nt][h * 2 + 0] + b0;
                float x1 = acc[mt][nt][h * 2 + 1] + b1;
                if (EPI == EPI_BN_RELU) {
                    x0 = fmaxf((x0 - m0) * g0 + be0, 0.f);
                    x1 = fmaxf((x1 - m1) * g1 + be1, 0.f);
                } else if (EPI == EPI_RES) {
                    __half2 rv = *(const __half2*)(res + off);
                    x0 = (x0 - m0) * g0 + be0 + __half2float(rv.x);
                    x1 = (x1 - m1) * g1 + be1 + __half2float(rv.y);
                }
                __half2 ov; ov.x = __float2half_rn(x0); ov.y = __float2half_rn(x1);
                *(__half2*)(out0 + off) = ov;
            }
        }
    }
}

// ================= fp8 e4m3 GEMM (decoder): 256 thr, frag double-buffer =================
#define QBK   128
#define QA_STR 144
#define QAS   (128 * QA_STR)
#define QBS   (256 * QA_STR)
#define SMEM_Q (3 * (QAS + QBS))

template<int EPI, bool QRELU, bool WH16>
__global__ void __launch_bounds__(256, 1)
gemm_q(const uint8_t* __restrict__ Ain, const uint8_t* __restrict__ WT,
       const float* __restrict__ bias,
       const float* __restrict__ gamma, const float* __restrict__ beta,
       const float* __restrict__ mean,  const float* __restrict__ var,
       const __half* __restrict__ res,
       void* __restrict__ out0, uint8_t* __restrict__ out1,
       int M, int N, int K)
{
    extern __shared__ char smem[];
    const uint32_t s_a = (uint32_t)__cvta_generic_to_shared(smem);
    const uint32_t s_b = s_a + 3 * QAS;

    const int tid  = threadIdx.x;
    const int lane = tid & 31;
    const int warp = tid >> 5;
    const int wm   = warp >> 2;
    const int wn   = warp & 3;
    const int row0 = blockIdx.y * 128;
    const int col0 = blockIdx.x * 256;
    const int l4   = lane >> 2;
    const int lm   = lane & 3;
    const int t8   = lane >> 3;
    const int jr   = lane & 7;

    uint32_t aBase[4], bBase[4];
#pragma unroll
    for (int mt = 0; mt < 4; mt++) {
        int r = wm * 64 + mt * 16 + ((t8 & 1) << 3) + jr;
        int cB = (t8 >> 1) << 4;
        aBase[mt] = s_a + (uint32_t)(r * QA_STR + cB);
    }
#pragma unroll
    for (int p = 0; p < 4; p++) {
        int r = wn * 64 + (2 * p + (t8 >> 1)) * 8 + jr;
        int cB = (t8 & 1) << 4;
        bBase[p] = s_b + (uint32_t)(r * QA_STR + cB);
    }

    float acc[4][8][4];
#pragma unroll
    for (int mt = 0; mt < 4; mt++)
#pragma unroll
        for (int nt = 0; nt < 8; nt++)
#pragma unroll
            for (int q = 0; q < 4; q++) acc[mt][nt][q] = 0.f;

    const int iters = K / QBK;

    auto loadA = [&](int s, int k0) {
#pragma unroll
        for (int i = 0; i < 4; i++) {
            int idx = i * 256 + tid;
            int r = idx >> 3, c16 = idx & 7;
            cp16(s_a + (uint32_t)(s * QAS) + (uint32_t)(r * QA_STR + c16 * 16),
                 Ain + (size_t)(row0 + r) * K + k0 + c16 * 16);
        }
    };
    auto loadB = [&](int s, int k0) {
#pragma unroll
        for (int i = 0; i < 8; i++) {
            int idx = i * 256 + tid;
            int n = idx >> 3, c16 = idx & 7;
            cp16(s_b + (uint32_t)(s * QBS) + (uint32_t)(n * QA_STR + c16 * 16),
                 WT + (size_t)(col0 + n) * K + k0 + c16 * 16);
        }
    };

    loadA(0, 0); loadB(0, 0); cp_commit();
    loadA(1, QBK); loadB(1, QBK); cp_commit();

    for (int it = 0; it < iters; it++) {
        if (it + 1 < iters) cp_wait<1>(); else cp_wait<0>();
        __syncthreads();
        if (it + 2 < iters) {
            int ps = (it + 2) % 3;
            loadA(ps, (it + 2) * QBK);
            loadB(ps, (it + 2) * QBK);
            cp_commit();
        }

        const int s = it % 3;
        const uint32_t aOff = (uint32_t)(s * QAS);
        const uint32_t bOff = (uint32_t)(s * QBS);

        uint32_t af[2][4][4], bf[2][8][2];
        auto ldfrag = [&](int buf, int kk) {
#pragma unroll
            for (int mt = 0; mt < 4; mt++)
                ldsm4(af[buf][mt][0], af[buf][mt][1], af[buf][mt][2], af[buf][mt][3],
                      aBase[mt] + aOff + (uint32_t)kk);
#pragma unroll
            for (int p = 0; p < 4; p++)
                ldsm4(bf[buf][2 * p][0], bf[buf][2 * p][1],
                      bf[buf][2 * p + 1][0], bf[buf][2 * p + 1][1],
                      bBase[p] + bOff + (uint32_t)kk);
        };

        ldfrag(0, 0);
#pragma unroll
        for (int ks = 0; ks < 4; ks++) {
            const int cur = ks & 1;
            if (ks < 3) ldfrag(cur ^ 1, (ks + 1) * 32);
#pragma unroll
            for (int mt = 0; mt < 4; mt++)
#pragma unroll
                for (int nt = 0; nt < 8; nt++)
                    mmaq(acc[mt][nt], af[cur][mt], bf[cur][nt]);
        }
    }

    // ---- epilogue ----
#pragma unroll
    for (int nt = 0; nt < 8; nt++) {
        int c = col0 + wn * 64 + nt * 8 + (lm << 1);
        float b0 = bias[c], b1 = bias[c + 1];
        float g0 = 0.f, g1 = 0.f, be0 = 0.f, be1 = 0.f, m0 = 0.f, m1 = 0.f;
        if (EPI == EPI_RES) {
            g0 = gamma[c]     * rsqrtf(var[c]     + 1e-5f);
            g1 = gamma[c + 1] * rsqrtf(var[c + 1] + 1e-5f);
            be0 = beta[c]; be1 = beta[c + 1];
            m0 = mean[c]; m1 = mean[c + 1];
        }
#pragma unroll
        for (int mt = 0; mt < 4; mt++) {
#pragma unroll
            for (int h = 0; h < 2; h++) {
                int r = row0 + wm * 64 + mt * 16 + l4 + h * 8;
                size_t off = (size_t)r * N + c;
                float x0 = acc[mt][nt][h * 2 + 0] * QSCALE_INV + b0;
                float x1 = acc[mt][nt][h * 2 + 1] * QSCALE_INV + b1;
                if (EPI == EPI_SIG) {
                    float* o = (float*)out0;
                    o[off]     = 1.f / (1.f + expf(-x0));
                    o[off + 1] = 1.f / (1.f + expf(-x1));
                    continue;
                }
                __half2 rv = *(const __half2*)(res + off);
                x0 = (x0 - m0) * g0 + be0 + __half2float(rv.x);
                x1 = (x1 - m1) * g1 + be1 + __half2float(rv.y);
                if (WH16) {
                    __half2 ov; ov.x = __float2half_rn(x0); ov.y = __float2half_rn(x1);
                    *(__half2*)((__half*)out0 + off) = ov;
                }
                float q0 = QRELU ? fmaxf(x0, 0.f) * QSCALE : x0 * QSCALE;
                float q1 = QRELU ? fmaxf(x1, 0.f) * QSCALE : x1 * QSCALE;
                *(uint16_t*)(out1 + off) = pack_q2(q0, q1);
            }
        }
    }
}

// ================= VQ: fp16 mma distances + argmin + fused gather/loss =================
#define AZ_STR 264
#define VQ_SMEM (128 * AZ_STR * 2 + 3 * HBS * 2)

__global__ void __launch_bounds__(256, 1)
vq_h(const __half* __restrict__ Z, const __half* __restrict__ CBH,
     const float* __restrict__ CB,
     __half* __restrict__ HQ, uint8_t* __restrict__ Q)
{
    extern __shared__ char smem[];
    __half* Az = (__half*)smem;
    __half* Bh = (__half*)(smem + 128 * AZ_STR * 2);
    const uint32_t s_az = (uint32_t)__cvta_generic_to_shared(Az);
    const uint32_t s_b  = (uint32_t)__cvta_generic_to_shared(Bh);
    __shared__ float sv[128][4];
    __shared__ int   si[128][4];
    __shared__ int   sidx[128];
    __shared__ float ws[8];

    const int tid  = threadIdx.x;
    const int lane = tid & 31;
    const int warp = tid >> 5;
    const int wm   = warp >> 2;
    const int wn   = warp & 3;
    const int row0 = blockIdx.x * 128;
    const int l4   = lane >> 2;
    const int lm   = lane & 3;
    const int t8   = lane >> 3;
    const int jr   = lane & 7;

    uint32_t aBase[4], bBase[4];
#pragma unroll
    for (int mt = 0; mt < 4; mt++) {
        int r = wm * 64 + mt * 16 + ((t8 & 1) << 3) + jr;
        int c = (t8 >> 1) << 3;
        aBase[mt] = s_az + (uint32_t)(r * AZ_STR + c) * 2;
    }
#pragma unroll
    for (int p = 0; p < 4; p++) {
        int r = wn * 64 + (2 * p + (t8 >> 1)) * 8 + jr;
        int c = (t8 & 1) << 3;
        bBase[p] = s_b + (uint32_t)(r * HA_STR + c) * 2;
    }

    auto loadB = [&](int s, int chunk) {
        int ct = chunk >> 2, k0 = (chunk & 3) * 64;
#pragma unroll
        for (int i = 0; i < 8; i++) {
            int idx = i * 256 + tid;
            int code = idx >> 3, kc = (idx & 7) << 3;
            cp16(s_b + (uint32_t)(s * (HBS * 2)) + (uint32_t)(code * HA_STR + kc) * 2,
                 CBH + (size_t)(ct * 256 + code) * NCD + k0 + kc);
        }
    };

#pragma unroll
    for (int i = 0; i < 16; i++) {
        int idx = i * 256 + tid;
        int r = idx >> 5, kc = (idx & 31) << 3;
        cp16(s_az + (uint32_t)(r * AZ_STR + kc) * 2,
             Z + (size_t)(row0 + r) * NCD + kc);
    }
    loadB(0, 0); cp_commit();
    loadB(1, 1); cp_commit();

    float minv[4][2];
    int   mini[4][2];
#pragma unroll
    for (int mt = 0; mt < 4; mt++)
#pragma unroll
        for (int h = 0; h < 2; h++) { minv[mt][h] = 3.4e38f; mini[mt][h] = 0; }

    float acc[4][8][4];
#pragma unroll
    for (int mt = 0; mt < 4; mt++)
#pragma unroll
        for (int nt = 0; nt < 8; nt++)
#pragma unroll
            for (int q = 0; q < 4; q++) acc[mt][nt][q] = 0.f;

    for (int c = 0; c < 64; c++) {
        if (c + 1 < 64) cp_wait<1>(); else cp_wait<0>();
        __syncthreads();
        if (c + 2 < 64) { loadB((c + 2) % 3, c + 2); cp_commit(); }

        const int s = c % 3;
        const uint32_t bOff = (uint32_t)(s * (HBS * 2));
        const int kg = (c & 3) * 64;

        uint32_t af[2][4][4], bf[2][8][2];
        auto ldfrag = [&](int buf, int kk) {
#pragma unroll
            for (int mt = 0; mt < 4; mt++)
                ldsm4(af[buf][mt][0], af[buf][mt][1], af[buf][mt][2], af[buf][mt][3],
                      aBase[mt] + (uint32_t)(kg + kk) * 2);
#pragma unroll
            for (int p = 0; p < 4; p++)
                ldsm4(bf[buf][2 * p][0], bf[buf][2 * p][1],
                      bf[buf][2 * p + 1][0], bf[buf][2 * p + 1][1],
                      bBase[p] + bOff + (uint32_t)kk * 2);
        };

        ldfrag(0, 0);
#pragma unroll
        for (int ks = 0; ks < 4; ks++) {
            const int cur = ks & 1;
            if (ks < 3) ldfrag(cur ^ 1, (ks + 1) * 16);
#pragma unroll
            for (int mt = 0; mt < 4; mt++)
#pragma unroll
                for (int nt = 0; nt < 8; nt++)
                    mma16(acc[mt][nt], af[cur][mt], bf[cur][nt]);
        }

        if ((c & 3) == 3) {
            int ct = (c >> 2) * 256;
#pragma unroll
            for (int nt = 0; nt < 8; nt++) {
                int code = ct + wn * 64 + nt * 8 + (lm << 1);
                float cn0 = g_cnorm[code], cn1 = g_cnorm[code + 1];
#pragma unroll
                for (int mt = 0; mt < 4; mt++)
#pragma unroll
                    for (int h = 0; h < 2; h++) {
                        float d0 = cn0 - 2.f * acc[mt][nt][h * 2 + 0];
                        float d1 = cn1 - 2.f * acc[mt][nt][h * 2 + 1];
                        if (d0 < minv[mt][h]) { minv[mt][h] = d0; mini[mt][h] = code; }
                        if (d1 < minv[mt][h]) { minv[mt][h] = d1; mini[mt][h] = code + 1; }
                        acc[mt][nt][h * 2 + 0] = 0.f;
                        acc[mt][nt][h * 2 + 1] = 0.f;
                    }
            }
        }
    }

#pragma unroll
    for (int mt = 0; mt < 4; mt++)
#pragma unroll
        for (int h = 0; h < 2; h++) {
            float v = minv[mt][h]; int ix = mini[mt][h];
#pragma unroll
            for (int o = 1; o <= 2; o <<= 1) {
                float vo = __shfl_xor_sync(0xffffffffu, v, o);
                int   io = __shfl_xor_sync(0xffffffffu, ix, o);
                if (vo < v || (vo == v && io < ix)) { v = vo; ix = io; }
            }
            if (lm == 0) {
                int rl = wm * 64 + mt * 16 + l4 + h * 8;
                sv[rl][wn] = v; si[rl][wn] = ix;
            }
        }
    __syncthreads();
    if (tid < 128) {
        float bv = sv[tid][0]; int bi = si[tid][0];
#pragma unroll
        for (int t = 1; t < 4; t++) {
            float v = sv[tid][t]; int k2 = si[tid][t];
            if (v < bv || (v == bv && k2 < bi)) { bv = v; bi = k2; }
        }
        sidx[tid] = bi;
        atomicAdd(&g_cnt[bi], 1);
    }
    __syncthreads();

    // ---- fused gather + loss ----
    float s = 0.f;
#pragma unroll 4
    for (int i = 0; i < 16; i++) {
        int r = warp * 16 + i;
        int id = sidx[r];
        const float* q = CB + (size_t)id * NCD;
        __half*  o  = HQ + (size_t)(row0 + r) * NCD;
        uint8_t* oq = Q  + (size_t)(row0 + r) * NCD;
#pragma unroll
        for (int e = 0; e < 8; e++) {
            int d = e * 32 + lane;
            float qq = q[d];
            float zz = __half2float(Az[r * AZ_STR + d]);
            o[d]  = __float2half_rn(qq);
            oq[d] = (uint8_t)__nv_cvt_float_to_fp8(fmaxf(qq, 0.f) * QSCALE,
                                                   __NV_SATFINITE, __NV_E4M3);
            float t = qq - zz;
            s += t * t;
        }
    }
#pragma unroll
    for (int o = 16; o > 0; o >>= 1) s += __shfl_xor_sync(0xffffffffu, s, o);
    if (lane == 0) ws[warp] = s;
    __syncthreads();
    if (tid == 0) {
        float t = 0.f;
#pragma unroll
        for (int w = 0; w < 8; w++) t += ws[w];
        g_losspart[blockIdx.x] = t;
    }
}

// ---------------- pre-pass kernels ----------------
__global__ void cvt_x(const float* __restrict__ in, __half* __restrict__ out, int n4)
{
    int i = blockIdx.x * 256 + threadIdx.x;
    if (i < n4) {
        float4 v = ((const float4*)in)[i];
        ((__half2*)out)[2 * i]     = __floats2half2_rn(v.x, v.y);
        ((__half2*)out)[2 * i + 1] = __floats2half2_rn(v.z, v.w);
    }
}

__global__ __launch_bounds__(256)
void prep_cb(const float* __restrict__ CB, __half* __restrict__ CBH)
{
    int warp = threadIdx.x >> 5, lane = threadIdx.x & 31;
    int code = blockIdx.x * 8 + warp;
    const float* c = CB + (size_t)code * NCD;
    __half* ch = CBH + (size_t)code * NCD;
    float s = 0.f;
#pragma unroll
    for (int e = 0; e < 8; e++) {
        int d = e * 32 + lane;
        __half hv = __float2half_rn(c[d]);
        ch[d] = hv;
        float v = __half2float(hv);
        s += v * v;
    }
#pragma unroll
    for (int o = 16; o > 0; o >>= 1) s += __shfl_xor_sync(0xffffffffu, s, o);
    if (lane == 0) { g_cnorm[code] = s; g_cnt[code] = 0; }
}

__global__ void transpose_f16(const float* __restrict__ W, __half* __restrict__ WT,
                              int K, int N)
{
    __shared__ float t[32][33];
    int n0 = blockIdx.x * 32, k0 = blockIdx.y * 32;
    int tx = threadIdx.x, ty = threadIdx.y;
#pragma unroll
    for (int i = 0; i < 32; i += 8)
        t[ty + i][tx] = W[(size_t)(k0 + ty + i) * N + n0 + tx];
    __syncthreads();
#pragma unroll
    for (int i = 0; i < 32; i += 8)
        WT[(size_t)(n0 + ty + i) * K + k0 + tx] = __float2half_rn(t[tx][ty + i]);
}

__global__ void transpose_sq6(const float* __restrict__ W2, const float* __restrict__ rbW,
                              __half* __restrict__ dh, uint8_t* __restrict__ dq)
{
    __shared__ float t[32][33];
    int z = blockIdx.z;
    const float* src = (z == 0) ? W2 : rbW + (size_t)(z - 1) * NEMB * NEMB;
    int n0 = blockIdx.x * 32, k0 = blockIdx.y * 32;
    int tx = threadIdx.x, ty = threadIdx.y;
#pragma unroll
    for (int i = 0; i < 32; i += 8)
        t[ty + i][tx] = src[(size_t)(k0 + ty + i) * NEMB + n0 + tx];
    __syncthreads();
    if (z < 3) {
        __half* out = dh + (size_t)z * NEMB * NEMB;
#pragma unroll
        for (int i = 0; i < 32; i += 8)
            out[(size_t)(n0 + ty + i) * NEMB + k0 + tx] = __float2half_rn(t[tx][ty + i]);
    } else {
        uint8_t* out = dq + (size_t)(z - 3) * NEMB * NEMB;
#pragma unroll
        for (int i = 0; i < 32; i += 8)
            out[(size_t)(n0 + ty + i) * NEMB + k0 + tx] =
                (uint8_t)__nv_cvt_float_to_fp8(t[tx][ty + i], __NV_SATFINITE, __NV_E4M3);
    }
}

__global__ void transpose_q8(const float* __restrict__ W, uint8_t* __restrict__ WT,
                             int K, int N)
{
    __shared__ float t[32][33];
    int n0 = blockIdx.x * 32, k0 = blockIdx.y * 32;
    int tx = threadIdx.x, ty = threadIdx.y;
#pragma unroll
    for (int i = 0; i < 32; i += 8)
        t[ty + i][tx] = W[(size_t)(k0 + ty + i) * N + n0 + tx];
    __syncthreads();
#pragma unroll
    for (int i = 0; i < 32; i += 8)
        WT[(size_t)(n0 + ty + i) * K + k0 + tx] =
            (uint8_t)__nv_cvt_float_to_fp8(t[tx][ty + i], __NV_SATFINITE, __NV_E4M3);
}

__global__ __launch_bounds__(256)
void finalize_kernel(float* __restrict__ out)
{
    __shared__ float red[256];
    int tid = threadIdx.x;

    float s = (tid < NFLAT / 128) ? g_losspart[tid] : 0.f;
    red[tid] = s; __syncthreads();
    for (int o = 128; o > 0; o >>= 1) { if (tid < o) red[tid] += red[tid + o]; __syncthreads(); }
    float loss = red[0] * (1.25f / ((float)NB * (float)NEMB));
    __syncthreads();

    float e = 0.f;
    for (int i = tid; i < NK; i += 256) {
        float p = (float)g_cnt[i] * (1.0f / (float)NFLAT);
        e += p * logf(p + 1e-10f);
    }
    red[tid] = e; __syncthreads();
    for (int o = 128; o > 0; o >>= 1) { if (tid < o) red[tid] += red[tid + o]; __syncthreads(); }

    if (tid == 0) {
        out[0]            = loss;
        out[OUT_PERP_OFF] = expf(-red[0]);
    }
}

// ---------------- launch ----------------
extern "C" void kernel_launch(void* const* d_in, const int* in_sizes, int n_in,
                              void* d_out, int out_size)
{
    const float* x    = (const float*)d_in[0];
    const float* W1   = (const float*)d_in[1];
    const float* b1   = (const float*)d_in[2];
    const float* bn1g = (const float*)d_in[3];
    const float* bn1b = (const float*)d_in[4];
    const float* bn1m = (const float*)d_in[5];
    const float* bn1v = (const float*)d_in[6];
    const float* W2   = (const float*)d_in[7];
    const float* b2   = (const float*)d_in[8];
    const float* rbW  = (const float*)d_in[9];
    const float* rbb  = (const float*)d_in[10];
    const float* rbg  = (const float*)d_in[11];
    const float* rbbe = (const float*)d_in[12];
    const float* rbm  = (const float*)d_in[13];
    const float* rbv  = (const float*)d_in[14];
    const float* cb   = (const float*)d_in[15];
    const float* decW = (const float*)d_in[16];
    const float* decb = (const float*)d_in[17];
    float* out = (float*)d_out;

    __half *xh, *w1t, *wts, *cbh, *ha, *har, *hb, *gz;
    uint8_t *wq, *wqd, *q1, *q2;
    cudaGetSymbolAddress((void**)&xh,  g_xh);
    cudaGetSymbolAddress((void**)&w1t, g_w1t);
    cudaGetSymbolAddress((void**)&wts, g_wts);
    cudaGetSymbolAddress((void**)&wq,  g_wq);
    cudaGetSymbolAddress((void**)&wqd, g_wqd);
    cudaGetSymbolAddress((void**)&cbh, g_cbh);
    cudaGetSymbolAddress((void**)&ha,  g_ha);
    cudaGetSymbolAddress((void**)&har, g_har);
    cudaGetSymbolAddress((void**)&hb,  g_hb);
    cudaGetSymbolAddress((void**)&gz,  g_z);
    cudaGetSymbolAddress((void**)&q1,  g_q1);
    cudaGetSymbolAddress((void**)&q2,  g_q2);

    cudaFuncSetAttribute(gemm_h<EPI_BN_RELU, false>, cudaFuncAttributeMaxDynamicSharedMemorySize, SMEM_H16);
    cudaFuncSetAttribute(gemm_h<EPI_BIAS,    false>, cudaFuncAttributeMaxDynamicSharedMemorySize, SMEM_H16);
    cudaFuncSetAttribute(gemm_h<EPI_RES,     true >, cudaFuncAttributeMaxDynamicSharedMemorySize, SMEM_H16);
    cudaFuncSetAttribute(gemm_q<EPI_RES,  true,  true >, cudaFuncAttributeMaxDynamicSharedMemorySize, SMEM_Q);
    cudaFuncSetAttribute(gemm_q<EPI_RES,  false, false>, cudaFuncAttributeMaxDynamicSharedMemorySize, SMEM_Q);
    cudaFuncSetAttribute(gemm_q<EPI_SIG,  false, false>, cudaFuncAttributeMaxDynamicSharedMemorySize, SMEM_Q);
    cudaFuncSetAttribute(vq_h, cudaFuncAttributeMaxDynamicSharedMemorySize, VQ_SMEM);

    const size_t WS = (size_t)NEMB * NEMB;
    dim3 tb(32, 8);
    dim3 blk(256);
    dim3 gE(NEMB / 256, NB / 128);   // 4 x 32
    dim3 gD(NIN / 256,  NB / 128);   // 32 x 32

    // pre-pass
    cvt_x<<<(NB * NIN / 4 + 255) / 256, 256>>>(x, xh, NB * NIN / 4);
    transpose_f16<<<dim3(NEMB / 32, NIN / 32),  tb>>>(W1, w1t, NIN, NEMB);
    transpose_sq6<<<dim3(32, 32, 6), tb>>>(W2, rbW, wts, wq);
    transpose_q8<<<dim3(NIN / 32, NEMB / 32), tb>>>(decW, wqd, NEMB, NIN);

    __half* w2t = wts + 0 * WS;
    __half* wt0 = wts + 1 * WS;
    __half* wt1 = wts + 2 * WS;

    // encoder (all pure fp16 ldsm path)
    gemm_h<EPI_BN_RELU, false><<<gE, blk, SMEM_H16>>>(
        xh, w1t, b1, bn1g, bn1b, bn1m, bn1v, nullptr, ha, NB, NEMB, NIN);
    gemm_h<EPI_BIAS, false><<<gE, blk, SMEM_H16>>>(
        ha, w2t, b2, nullptr, nullptr, nullptr, nullptr, nullptr, hb, NB, NEMB, NEMB);
    gemm_h<EPI_RES, true><<<gE, blk, SMEM_H16>>>(
        hb, wt0, rbb + 0 * NEMB, rbg + 0 * NEMB, rbbe + 0 * NEMB,
        rbm + 0 * NEMB, rbv + 0 * NEMB, hb, har, NB, NEMB, NEMB);
    gemm_h<EPI_RES, true><<<gE, blk, SMEM_H16>>>(
        har, wt1, rbb + 1 * NEMB, rbg + 1 * NEMB, rbbe + 1 * NEMB,
        rbm + 1 * NEMB, rbv + 1 * NEMB, har, gz, NB, NEMB, NEMB);

    // vector quantizer (distances + argmin + fused gather/loss)
    prep_cb<<<NK / 8, 256>>>(cb, cbh);
    vq_h<<<NFLAT / 128, blk, VQ_SMEM>>>(gz, cbh, cb, hb, q1);
    finalize_kernel<<<1, 256>>>(out);

    // decoder (fp8 e4m3 mma, activations scaled by 4096)
    gemm_q<EPI_RES, true, true><<<gE, blk, SMEM_Q>>>(
        q1, wq + 0 * WS, rbb + 2 * NEMB, rbg + 2 * NEMB, rbbe + 2 * NEMB,
        rbm + 2 * NEMB, rbv + 2 * NEMB, hb, ha, q2, NB, NEMB, NEMB);
    gemm_q<EPI_RES, true, true><<<gE, blk, SMEM_Q>>>(
        q2, wq + 1 * WS, rbb + 3 * NEMB, rbg + 3 * NEMB, rbbe + 3 * NEMB,
        rbm + 3 * NEMB, rbv + 3 * NEMB, ha, hb, q1, NB, NEMB, NEMB);
    gemm_q<EPI_RES, false, false><<<gE, blk, SMEM_Q>>>(
        q1, wq + 2 * WS, rbb + 4 * NEMB, rbg + 4 * NEMB, rbbe + 4 * NEMB,
        rbm + 4 * NEMB, rbv + 4 * NEMB, hb, nullptr, q2, NB, NEMB, NEMB);
    gemm_q<EPI_SIG, false, false><<<gD, blk, SMEM_Q>>>(
        q2, wqd, decb, nullptr, nullptr, nullptr, nullptr, nullptr,
        out + 1, nullptr, NB, NIN, NEMB);
}

// round 15
// speedup vs baseline: 1.5110x; 1.5110x over previous
#include <cuda_runtime.h>
#include <cuda_fp16.h>
#include <cuda_fp8.h>
#include <math.h>
#include <stdint.h>

// ---------------- problem dims ----------------
#define NB    4096
#define NIN   8192
#define NEMB  1024
#define NK    4096
#define NCD   256
#define NFLAT 16384
#define OUT_PERP_OFF ((size_t)1 + (size_t)NB * (size_t)NIN)

#define EPI_BN_RELU 0
#define EPI_BIAS    1
#define EPI_RES     2
#define EPI_SIG     3

#define QSCALE     4096.0f
#define QSCALE_INV 0.000244140625f

// ---------------- scratch (device globals) ----------------
__device__ __half  g_xh [(size_t)NB * NIN];
__device__ __half  g_w1t[(size_t)NIN * NEMB];
__device__ __half  g_wts[(size_t)3 * NEMB * NEMB];    // W2, rb0, rb1 (fp16, [n][k])
__device__ uint8_t g_wq [(size_t)3 * NEMB * NEMB];    // rb2, rb3, rb4 (e4m3, [n][k])
__device__ uint8_t g_wqd[(size_t)NIN * NEMB];         // decW (e4m3, [n][k])
__device__ __half  g_cbh[(size_t)NK * NCD];
__device__ __half  g_ha [(size_t)NB * NEMB];
__device__ __half  g_har[(size_t)NB * NEMB];
__device__ __half  g_hb [(size_t)NB * NEMB];
__device__ __half  g_z  [(size_t)NB * NEMB];
__device__ uint8_t g_q1 [(size_t)NB * NEMB];
__device__ uint8_t g_q2 [(size_t)NB * NEMB];
__device__ float   g_cnorm[NK];
__device__ int     g_cnt[NK];
__device__ float   g_losspart[NFLAT / 128];

// ---------------- helpers ----------------
__device__ __forceinline__ void cp16(uint32_t dst, const void* src) {
    asm volatile("cp.async.cg.shared.global [%0], [%1], 16;" :: "r"(dst), "l"(src));
}
__device__ __forceinline__ void cp_commit() {
    asm volatile("cp.async.commit_group;");
}
template<int N>
__device__ __forceinline__ void cp_wait() {
    asm volatile("cp.async.wait_group %0;" :: "n"(N));
}
__device__ __forceinline__ void mma16(float* c, const uint32_t* a, const uint32_t* b) {
    asm volatile(
        "mma.sync.aligned.m16n8k16.row.col.f32.f16.f16.f32 "
        "{%0,%1,%2,%3},{%4,%5,%6,%7},{%8,%9},{%0,%1,%2,%3};"
        : "+f"(c[0]), "+f"(c[1]), "+f"(c[2]), "+f"(c[3])
        : "r"(a[0]), "r"(a[1]), "r"(a[2]), "r"(a[3]), "r"(b[0]), "r"(b[1]));
}
__device__ __forceinline__ void mmaq(float* c, const uint32_t* a, const uint32_t* b) {
    asm volatile(
        "mma.sync.aligned.m16n8k32.row.col.f32.e4m3.e4m3.f32 "
        "{%0,%1,%2,%3},{%4,%5,%6,%7},{%8,%9},{%0,%1,%2,%3};"
        : "+f"(c[0]), "+f"(c[1]), "+f"(c[2]), "+f"(c[3])
        : "r"(a[0]), "r"(a[1]), "r"(a[2]), "r"(a[3]), "r"(b[0]), "r"(b[1]));
}
__device__ __forceinline__ void ldsm4(uint32_t& r0, uint32_t& r1, uint32_t& r2, uint32_t& r3,
                                      uint32_t addr) {
    asm volatile("ldmatrix.sync.aligned.m8n8.x4.shared.b16 {%0,%1,%2,%3}, [%4];"
                 : "=r"(r0), "=r"(r1), "=r"(r2), "=r"(r3) : "r"(addr));
}
__device__ __forceinline__ uint16_t pack_q2(float lo, float hi) {
    uint16_t r;
    asm("cvt.rn.satfinite.e4m3x2.f32 %0, %1, %2;" : "=h"(r) : "f"(hi), "f"(lo));
    return r;
}
__device__ __forceinline__ uint32_t relu_h2(uint32_t v) {
    __half2 h = *(__half2*)&v;
    h = __hmax2(h, __float2half2_rn(0.f));
    return *(uint32_t*)&h;
}

// ================= fp16 tensor-core GEMM (256 thr, 3-stage, ldmatrix) =================
#define HBK   64
#define HA_STR 72
#define HAS   (128 * HA_STR)
#define HBS   (256 * HA_STR)
#define SMEM_H16 (3 * (HAS * 2 + HBS * 2))

template<int EPI, bool RELUA>
__global__ void __launch_bounds__(256, 1)
gemm_h(const __half* __restrict__ Ain, const __half* __restrict__ WT,
       const float* __restrict__ bias,
       const float* __restrict__ gamma, const float* __restrict__ beta,
       const float* __restrict__ mean,  const float* __restrict__ var,
       const __half* __restrict__ res,
       __half* __restrict__ out0,
       int M, int N, int K)
{
    extern __shared__ char smem[];
    const int ASTG = HAS * 2;
    const int BSTG = HBS * 2;
    __half* Bh = (__half*)(smem + 3 * ASTG);
    const uint32_t s_a = (uint32_t)__cvta_generic_to_shared(smem);
    const uint32_t s_b = (uint32_t)__cvta_generic_to_shared(Bh);

    const int tid  = threadIdx.x;
    const int lane = tid & 31;
    const int warp = tid >> 5;
    const int wm   = warp >> 2;
    const int wn   = warp & 3;
    const int row0 = blockIdx.y * 128;
    const int col0 = blockIdx.x * 256;
    const int l4   = lane >> 2;
    const int lm   = lane & 3;
    const int t8   = lane >> 3;
    const int jr   = lane & 7;

    uint32_t aBase[4], bBase[4];
#pragma unroll
    for (int mt = 0; mt < 4; mt++) {
        int r = wm * 64 + mt * 16 + ((t8 & 1) << 3) + jr;
        int c = (t8 >> 1) << 3;
        aBase[mt] = s_a + (uint32_t)(r * HA_STR + c) * 2;
    }
#pragma unroll
    for (int p = 0; p < 4; p++) {
        int r = wn * 64 + (2 * p + (t8 >> 1)) * 8 + jr;
        int c = (t8 & 1) << 3;
        bBase[p] = s_b + (uint32_t)(r * HA_STR + c) * 2;
    }

    float acc[4][8][4];
#pragma unroll
    for (int mt = 0; mt < 4; mt++)
#pragma unroll
        for (int nt = 0; nt < 8; nt++)
#pragma unroll
            for (int q = 0; q < 4; q++) acc[mt][nt][q] = 0.f;

    const int iters = K / HBK;

    auto loadA = [&](int s, int k0) {
#pragma unroll
        for (int i = 0; i < 4; i++) {
            int idx = i * 256 + tid;
            int r = idx >> 3, kc = (idx & 7) << 3;
            cp16(s_a + (uint32_t)(s * ASTG) + (uint32_t)(r * HA_STR + kc) * 2,
                 Ain + (size_t)(row0 + r) * K + k0 + kc);
        }
    };
    auto loadB = [&](int s, int k0) {
#pragma unroll
        for (int i = 0; i < 8; i++) {
            int idx = i * 256 + tid;
            int n = idx >> 3, kc = (idx & 7) << 3;
            cp16(s_b + (uint32_t)(s * BSTG) + (uint32_t)(n * HA_STR + kc) * 2,
                 WT + (size_t)(col0 + n) * K + k0 + kc);
        }
    };

    loadA(0, 0); loadB(0, 0); cp_commit();
    loadA(1, HBK); loadB(1, HBK); cp_commit();

    for (int it = 0; it < iters; it++) {
        if (it + 1 < iters) cp_wait<1>(); else cp_wait<0>();
        __syncthreads();
        if (it + 2 < iters) {
            int ps = (it + 2) % 3;
            loadA(ps, (it + 2) * HBK);
            loadB(ps, (it + 2) * HBK);
            cp_commit();
        }

        const int s = it % 3;
        const uint32_t aOff = (uint32_t)(s * ASTG);
        const uint32_t bOff = (uint32_t)(s * BSTG);
#pragma unroll
        for (int kk = 0; kk < HBK; kk += 16) {
            uint32_t af[4][4], bf[8][2];
#pragma unroll
            for (int mt = 0; mt < 4; mt++) {
                ldsm4(af[mt][0], af[mt][1], af[mt][2], af[mt][3],
                      aBase[mt] + aOff + (uint32_t)kk * 2);
                if (RELUA) {
#pragma unroll
                    for (int i = 0; i < 4; i++) af[mt][i] = relu_h2(af[mt][i]);
                }
            }
#pragma unroll
            for (int p = 0; p < 4; p++)
                ldsm4(bf[2 * p][0], bf[2 * p][1], bf[2 * p + 1][0], bf[2 * p + 1][1],
                      bBase[p] + bOff + (uint32_t)kk * 2);
#pragma unroll
            for (int mt = 0; mt < 4; mt++)
#pragma unroll
                for (int nt = 0; nt < 8; nt++)
                    mma16(acc[mt][nt], af[mt], bf[nt]);
        }
    }

    // ---- epilogue (single fp16 output) ----
#pragma unroll
    for (int nt = 0; nt < 8; nt++) {
        int c = col0 + wn * 64 + nt * 8 + (lm << 1);
        float b0 = bias[c], b1 = bias[c + 1];
        float g0 = 0.f, g1 = 0.f, be0 = 0.f, be1 = 0.f, m0 = 0.f, m1 = 0.f;
        if (EPI == EPI_BN_RELU || EPI == EPI_RES) {
            g0 = gamma[c]     * rsqrtf(var[c]     + 1e-5f);
            g1 = gamma[c + 1] * rsqrtf(var[c + 1] + 1e-5f);
            be0 = beta[c]; be1 = beta[c + 1];
            m0 = mean[c]; m1 = mean[c + 1];
        }
#pragma unroll
        for (int mt = 0; mt < 4; mt++) {
#pragma unroll
            for (int h = 0; h < 2; h++) {
                int r = row0 + wm * 64 + mt * 16 + l4 + h * 8;
                size_t off = (size_t)r * N + c;
                float x0 = acc[mt][nt][h * 2 + 0] + b0;
                float x1 = acc[mt][nt][h * 2 + 1] + b1;
                if (EPI == EPI_BN_RELU) {
                    x0 = fmaxf((x0 - m0) * g0 + be0, 0.f);
                    x1 = fmaxf((x1 - m1) * g1 + be1, 0.f);
                } else if (EPI == EPI_RES) {
                    __half2 rv = *(const __half2*)(res + off);
                    x0 = (x0 - m0) * g0 + be0 + __half2float(rv.x);
                    x1 = (x1 - m1) * g1 + be1 + __half2float(rv.y);
                }
                __half2 ov; ov.x = __float2half_rn(x0); ov.y = __float2half_rn(x1);
                *(__half2*)(out0 + off) = ov;
            }
        }
    }
}

// ================= fp8 e4m3 GEMM (decoder): 256 thr =================
#define QBK   128
#define QA_STR 144
#define QAS   (128 * QA_STR)
#define QBS   (256 * QA_STR)
#define SMEM_Q (3 * (QAS + QBS))

template<int EPI, bool QRELU, bool WH16>
__global__ void __launch_bounds__(256, 1)
gemm_q(const uint8_t* __restrict__ Ain, const uint8_t* __restrict__ WT,
       const float* __restrict__ bias,
       const float* __restrict__ gamma, const float* __restrict__ beta,
       const float* __restrict__ mean,  const float* __restrict__ var,
       const __half* __restrict__ res,
       void* __restrict__ out0, uint8_t* __restrict__ out1,
       int M, int N, int K)
{
    extern __shared__ char smem[];
    const uint32_t s_a = (uint32_t)__cvta_generic_to_shared(smem);
    const uint32_t s_b = s_a + 3 * QAS;

    const int tid  = threadIdx.x;
    const int lane = tid & 31;
    const int warp = tid >> 5;
    const int wm   = warp >> 2;
    const int wn   = warp & 3;
    const int row0 = blockIdx.y * 128;
    const int col0 = blockIdx.x * 256;
    const int l4   = lane >> 2;
    const int lm   = lane & 3;
    const int t8   = lane >> 3;
    const int jr   = lane & 7;

    uint32_t aBase[4], bBase[4];
#pragma unroll
    for (int mt = 0; mt < 4; mt++) {
        int r = wm * 64 + mt * 16 + ((t8 & 1) << 3) + jr;
        int cB = (t8 >> 1) << 4;
        aBase[mt] = s_a + (uint32_t)(r * QA_STR + cB);
    }
#pragma unroll
    for (int p = 0; p < 4; p++) {
        int r = wn * 64 + (2 * p + (t8 >> 1)) * 8 + jr;
        int cB = (t8 & 1) << 4;
        bBase[p] = s_b + (uint32_t)(r * QA_STR + cB);
    }

    float acc[4][8][4];
#pragma unroll
    for (int mt = 0; mt < 4; mt++)
#pragma unroll
        for (int nt = 0; nt < 8; nt++)
#pragma unroll
            for (int q = 0; q < 4; q++) acc[mt][nt][q] = 0.f;

    const int iters = K / QBK;

    auto loadA = [&](int s, int k0) {
#pragma unroll
        for (int i = 0; i < 4; i++) {
            int idx = i * 256 + tid;
            int r = idx >> 3, c16 = idx & 7;
            cp16(s_a + (uint32_t)(s * QAS) + (uint32_t)(r * QA_STR + c16 * 16),
                 Ain + (size_t)(row0 + r) * K + k0 + c16 * 16);
        }
    };
    auto loadB = [&](int s, int k0) {
#pragma unroll
        for (int i = 0; i < 8; i++) {
            int idx = i * 256 + tid;
            int n = idx >> 3, c16 = idx & 7;
            cp16(s_b + (uint32_t)(s * QBS) + (uint32_t)(n * QA_STR + c16 * 16),
                 WT + (size_t)(col0 + n) * K + k0 + c16 * 16);
        }
    };

    loadA(0, 0); loadB(0, 0); cp_commit();
    loadA(1, QBK); loadB(1, QBK); cp_commit();

    for (int it = 0; it < iters; it++) {
        if (it + 1 < iters) cp_wait<1>(); else cp_wait<0>();
        __syncthreads();
        if (it + 2 < iters) {
            int ps = (it + 2) % 3;
            loadA(ps, (it + 2) * QBK);
            loadB(ps, (it + 2) * QBK);
            cp_commit();
        }

        const int s = it % 3;
        const uint32_t aOff = (uint32_t)(s * QAS);
        const uint32_t bOff = (uint32_t)(s * QBS);
#pragma unroll
        for (int kk = 0; kk < QBK; kk += 32) {
            uint32_t af[4][4], bf[8][2];
#pragma unroll
            for (int mt = 0; mt < 4; mt++)
                ldsm4(af[mt][0], af[mt][1], af[mt][2], af[mt][3],
                      aBase[mt] + aOff + (uint32_t)kk);
#pragma unroll
            for (int p = 0; p < 4; p++)
                ldsm4(bf[2 * p][0], bf[2 * p][1], bf[2 * p + 1][0], bf[2 * p + 1][1],
                      bBase[p] + bOff + (uint32_t)kk);
#pragma unroll
            for (int mt = 0; mt < 4; mt++)
#pragma unroll
                for (int nt = 0; nt < 8; nt++)
                    mmaq(acc[mt][nt], af[mt], bf[nt]);
        }
    }

    // ---- epilogue ----
#pragma unroll
    for (int nt = 0; nt < 8; nt++) {
        int c = col0 + wn * 64 + nt * 8 + (lm << 1);
        float b0 = bias[c], b1 = bias[c + 1];
        float g0 = 0.f, g1 = 0.f, be0 = 0.f, be1 = 0.f, m0 = 0.f, m1 = 0.f;
        if (EPI == EPI_RES) {
            g0 = gamma[c]     * rsqrtf(var[c]     + 1e-5f);
            g1 = gamma[c + 1] * rsqrtf(var[c + 1] + 1e-5f);
            be0 = beta[c]; be1 = beta[c + 1];
            m0 = mean[c]; m1 = mean[c + 1];
        }
#pragma unroll
        for (int mt = 0; mt < 4; mt++) {
#pragma unroll
            for (int h = 0; h < 2; h++) {
                int r = row0 + wm * 64 + mt * 16 + l4 + h * 8;
                size_t off = (size_t)r * N + c;
                float x0 = acc[mt][nt][h * 2 + 0] * QSCALE_INV + b0;
                float x1 = acc[mt][nt][h * 2 + 1] * QSCALE_INV + b1;
                if (EPI == EPI_SIG) {
                    float* o = (float*)out0;
                    o[off]     = 1.f / (1.f + expf(-x0));
                    o[off + 1] = 1.f / (1.f + expf(-x1));
                    continue;
                }
                __half2 rv = *(const __half2*)(res + off);
                x0 = (x0 - m0) * g0 + be0 + __half2float(rv.x);
                x1 = (x1 - m1) * g1 + be1 + __half2float(rv.y);
                if (WH16) {
                    __half2 ov; ov.x = __float2half_rn(x0); ov.y = __float2half_rn(x1);
                    *(__half2*)((__half*)out0 + off) = ov;
                }
                float q0 = QRELU ? fmaxf(x0, 0.f) * QSCALE : x0 * QSCALE;
                float q1 = QRELU ? fmaxf(x1, 0.f) * QSCALE : x1 * QSCALE;
                *(uint16_t*)(out1 + off) = pack_q2(q0, q1);
            }
        }
    }
}

// ================= VQ: fp16 mma distances + argmin + fused gather/loss =================
#define AZ_STR 264
#define VQ_SMEM (128 * AZ_STR * 2 + 3 * HBS * 2)

__global__ void __launch_bounds__(256, 1)
vq_h(const __half* __restrict__ Z, const __half* __restrict__ CBH,
     const float* __restrict__ CB,
     __half* __restrict__ HQ, uint8_t* __restrict__ Q)
{
    extern __shared__ char smem[];
    __half* Az = (__half*)smem;
    __half* Bh = (__half*)(smem + 128 * AZ_STR * 2);
    const uint32_t s_az = (uint32_t)__cvta_generic_to_shared(Az);
    const uint32_t s_b  = (uint32_t)__cvta_generic_to_shared(Bh);
    __shared__ float sv[128][4];
    __shared__ int   si[128][4];
    __shared__ int   sidx[128];
    __shared__ float ws[8];

    const int tid  = threadIdx.x;
    const int lane = tid & 31;
    const int warp = tid >> 5;
    const int wm   = warp >> 2;
    const int wn   = warp & 3;
    const int row0 = blockIdx.x * 128;
    const int l4   = lane >> 2;
    const int lm   = lane & 3;
    const int t8   = lane >> 3;
    const int jr   = lane & 7;

    uint32_t aBase[4], bBase[4];
#pragma unroll
    for (int mt = 0; mt < 4; mt++) {
        int r = wm * 64 + mt * 16 + ((t8 & 1) << 3) + jr;
        int c = (t8 >> 1) << 3;
        aBase[mt] = s_az + (uint32_t)(r * AZ_STR + c) * 2;
    }
#pragma unroll
    for (int p = 0; p < 4; p++) {
        int r = wn * 64 + (2 * p + (t8 >> 1)) * 8 + jr;
        int c = (t8 & 1) << 3;
        bBase[p] = s_b + (uint32_t)(r * HA_STR + c) * 2;
    }

    auto loadB = [&](int s, int chunk) {
        int ct = chunk >> 2, k0 = (chunk & 3) * 64;
#pragma unroll
        for (int i = 0; i < 8; i++) {
            int idx = i * 256 + tid;
            int code = idx >> 3, kc = (idx & 7) << 3;
            cp16(s_b + (uint32_t)(s * (HBS * 2)) + (uint32_t)(code * HA_STR + kc) * 2,
                 CBH + (size_t)(ct * 256 + code) * NCD + k0 + kc);
        }
    };

#pragma unroll
    for (int i = 0; i < 16; i++) {
        int idx = i * 256 + tid;
        int r = idx >> 5, kc = (idx & 31) << 3;
        cp16(s_az + (uint32_t)(r * AZ_STR + kc) * 2,
             Z + (size_t)(row0 + r) * NCD + kc);
    }
    loadB(0, 0); cp_commit();
    loadB(1, 1); cp_commit();

    float minv[4][2];
    int   mini[4][2];
#pragma unroll
    for (int mt = 0; mt < 4; mt++)
#pragma unroll
        for (int h = 0; h < 2; h++) { minv[mt][h] = 3.4e38f; mini[mt][h] = 0; }

    float acc[4][8][4];
#pragma unroll
    for (int mt = 0; mt < 4; mt++)
#pragma unroll
        for (int nt = 0; nt < 8; nt++)
#pragma unroll
            for (int q = 0; q < 4; q++) acc[mt][nt][q] = 0.f;

    for (int c = 0; c < 64; c++) {
        if (c + 1 < 64) cp_wait<1>(); else cp_wait<0>();
        __syncthreads();
        if (c + 2 < 64) { loadB((c + 2) % 3, c + 2); cp_commit(); }

        const int s = c % 3;
        const uint32_t bOff = (uint32_t)(s * (HBS * 2));
        const int kg = (c & 3) * 64;
#pragma unroll
        for (int kk = 0; kk < 64; kk += 16) {
            uint32_t af[4][4], bf[8][2];
#pragma unroll
            for (int mt = 0; mt < 4; mt++)
                ldsm4(af[mt][0], af[mt][1], af[mt][2], af[mt][3],
                      aBase[mt] + (uint32_t)(kg + kk) * 2);
#pragma unroll
            for (int p = 0; p < 4; p++)
                ldsm4(bf[2 * p][0], bf[2 * p][1], bf[2 * p + 1][0], bf[2 * p + 1][1],
                      bBase[p] + bOff + (uint32_t)kk * 2);
#pragma unroll
            for (int mt = 0; mt < 4; mt++)
#pragma unroll
                for (int nt = 0; nt < 8; nt++)
                    mma16(acc[mt][nt], af[mt], bf[nt]);
        }

        if ((c & 3) == 3) {
            int ct = (c >> 2) * 256;
#pragma unroll
            for (int nt = 0; nt < 8; nt++) {
                int code = ct + wn * 64 + nt * 8 + (lm << 1);
                float cn0 = g_cnorm[code], cn1 = g_cnorm[code + 1];
#pragma unroll
                for (int mt = 0; mt < 4; mt++)
#pragma unroll
                    for (int h = 0; h < 2; h++) {
                        float d0 = cn0 - 2.f * acc[mt][nt][h * 2 + 0];
                        float d1 = cn1 - 2.f * acc[mt][nt][h * 2 + 1];
                        if (d0 < minv[mt][h]) { minv[mt][h] = d0; mini[mt][h] = code; }
                        if (d1 < minv[mt][h]) { minv[mt][h] = d1; mini[mt][h] = code + 1; }
                        acc[mt][nt][h * 2 + 0] = 0.f;
                        acc[mt][nt][h * 2 + 1] = 0.f;
                    }
            }
        }
    }

#pragma unroll
    for (int mt = 0; mt < 4; mt++)
#pragma unroll
        for (int h = 0; h < 2; h++) {
            float v = minv[mt][h]; int ix = mini[mt][h];
#pragma unroll
            for (int o = 1; o <= 2; o <<= 1) {
                float vo = __shfl_xor_sync(0xffffffffu, v, o);
                int   io = __shfl_xor_sync(0xffffffffu, ix, o);
                if (vo < v || (vo == v && io < ix)) { v = vo; ix = io; }
            }
            if (lm == 0) {
                int rl = wm * 64 + mt * 16 + l4 + h * 8;
                sv[rl][wn] = v; si[rl][wn] = ix;
            }
        }
    __syncthreads();
    if (tid < 128) {
        float bv = sv[tid][0]; int bi = si[tid][0];
#pragma unroll
        for (int t = 1; t < 4; t++) {
            float v = sv[tid][t]; int k2 = si[tid][t];
            if (v < bv || (v == bv && k2 < bi)) { bv = v; bi = k2; }
        }
        sidx[tid] = bi;
        atomicAdd(&g_cnt[bi], 1);
    }
    __syncthreads();

    // ---- fused gather + loss ----
    float s = 0.f;
#pragma unroll 4
    for (int i = 0; i < 16; i++) {
        int r = warp * 16 + i;
        int id = sidx[r];
        const float* q = CB + (size_t)id * NCD;
        __half*  o  = HQ + (size_t)(row0 + r) * NCD;
        uint8_t* oq = Q  + (size_t)(row0 + r) * NCD;
#pragma unroll
        for (int e = 0; e < 8; e++) {
            int d = e * 32 + lane;
            float qq = q[d];
            float zz = __half2float(Az[r * AZ_STR + d]);
            o[d]  = __float2half_rn(qq);
            oq[d] = (uint8_t)__nv_cvt_float_to_fp8(fmaxf(qq, 0.f) * QSCALE,
                                                   __NV_SATFINITE, __NV_E4M3);
            float t = qq - zz;
            s += t * t;
        }
    }
#pragma unroll
    for (int o = 16; o > 0; o >>= 1) s += __shfl_xor_sync(0xffffffffu, s, o);
    if (lane == 0) ws[warp] = s;
    __syncthreads();
    if (tid == 0) {
        float t = 0.f;
#pragma unroll
        for (int w = 0; w < 8; w++) t += ws[w];
        g_losspart[blockIdx.x] = t;
    }
}

// ---------------- pre-pass kernels ----------------
__global__ void cvt_x(const float* __restrict__ in, __half* __restrict__ out, int n4)
{
    int i = blockIdx.x * 256 + threadIdx.x;
    if (i < n4) {
        float4 v = ((const float4*)in)[i];
        ((__half2*)out)[2 * i]     = __floats2half2_rn(v.x, v.y);
        ((__half2*)out)[2 * i + 1] = __floats2half2_rn(v.z, v.w);
    }
}

__global__ __launch_bounds__(256)
void prep_cb(const float* __restrict__ CB, __half* __restrict__ CBH)
{
    int warp = threadIdx.x >> 5, lane = threadIdx.x & 31;
    int code = blockIdx.x * 8 + warp;
    const float* c = CB + (size_t)code * NCD;
    __half* ch = CBH + (size_t)code * NCD;
    float s = 0.f;
#pragma unroll
    for (int e = 0; e < 8; e++) {
        int d = e * 32 + lane;
        __half hv = __float2half_rn(c[d]);
        ch[d] = hv;
        float v = __half2float(hv);
        s += v * v;
    }
#pragma unroll
    for (int o = 16; o > 0; o >>= 1) s += __shfl_xor_sync(0xffffffffu, s, o);
    if (lane == 0) { g_cnorm[code] = s; g_cnt[code] = 0; }
}

__global__ void transpose_f16(const float* __restrict__ W, __half* __restrict__ WT,
                              int K, int N)
{
    __shared__ float t[32][33];
    int n0 = blockIdx.x * 32, k0 = blockIdx.y * 32;
    int tx = threadIdx.x, ty = threadIdx.y;
#pragma unroll
    for (int i = 0; i < 32; i += 8)
        t[ty + i][tx] = W[(size_t)(k0 + ty + i) * N + n0 + tx];
    __syncthreads();
#pragma unroll
    for (int i = 0; i < 32; i += 8)
        WT[(size_t)(n0 + ty + i) * K + k0 + tx] = __float2half_rn(t[tx][ty + i]);
}

__global__ void transpose_sq6(const float* __restrict__ W2, const float* __restrict__ rbW,
                              __half* __restrict__ dh, uint8_t* __restrict__ dq)
{
    __shared__ float t[32][33];
    int z = blockIdx.z;
    const float* src = (z == 0) ? W2 : rbW + (size_t)(z - 1) * NEMB * NEMB;
    int n0 = blockIdx.x * 32, k0 = blockIdx.y * 32;
    int tx = threadIdx.x, ty = threadIdx.y;
#pragma unroll
    for (int i = 0; i < 32; i += 8)
        t[ty + i][tx] = src[(size_t)(k0 + ty + i) * NEMB + n0 + tx];
    __syncthreads();
    if (z < 3) {
        __half* out = dh + (size_t)z * NEMB * NEMB;
#pragma unroll
        for (int i = 0; i < 32; i += 8)
            out[(size_t)(n0 + ty + i) * NEMB + k0 + tx] = __float2half_rn(t[tx][ty + i]);
    } else {
        uint8_t* out = dq + (size_t)(z - 3) * NEMB * NEMB;
#pragma unroll
        for (int i = 0; i < 32; i += 8)
            out[(size_t)(n0 + ty + i) * NEMB + k0 + tx] =
                (uint8_t)__nv_cvt_float_to_fp8(t[tx][ty + i], __NV_SATFINITE, __NV_E4M3);
    }
}

__global__ void transpose_q8(const float* __restrict__ W, uint8_t* __restrict__ WT,
                             int K, int N)
{
    __shared__ float t[32][33];
    int n0 = blockIdx.x * 32, k0 = blockIdx.y * 32;
    int tx = threadIdx.x, ty = threadIdx.y;
#pragma unroll
    for (int i = 0; i < 32; i += 8)
        t[ty + i][tx] = W[(size_t)(k0 + ty + i) * N + n0 + tx];
    __syncthreads();
#pragma unroll
    for (int i = 0; i < 32; i += 8)
        WT[(size_t)(n0 + ty + i) * K + k0 + tx] =
            (uint8_t)__nv_cvt_float_to_fp8(t[tx][ty + i], __NV_SATFINITE, __NV_E4M3);
}

__global__ __launch_bounds__(256)
void finalize_kernel(float* __restrict__ out)
{
    __shared__ float red[256];
    int tid = threadIdx.x;

    float s = (tid < NFLAT / 128) ? g_losspart[tid] : 0.f;
    red[tid] = s; __syncthreads();
    for (int o = 128; o > 0; o >>= 1) { if (tid < o) red[tid] += red[tid + o]; __syncthreads(); }
    float loss = red[0] * (1.25f / ((float)NB * (float)NEMB));
    __syncthreads();

    float e = 0.f;
    for (int i = tid; i < NK; i += 256) {
        float p = (float)g_cnt[i] * (1.0f / (float)NFLAT);
        e += p * logf(p + 1e-10f);
    }
    red[tid] = e; __syncthreads();
    for (int o = 128; o > 0; o >>= 1) { if (tid < o) red[tid] += red[tid + o]; __syncthreads(); }

    if (tid == 0) {
        out[0]            = loss;
        out[OUT_PERP_OFF] = expf(-red[0]);
    }
}

// ---------------- launch ----------------
extern "C" void kernel_launch(void* const* d_in, const int* in_sizes, int n_in,
                              void* d_out, int out_size)
{
    const float* x    = (const float*)d_in[0];
    const float* W1   = (const float*)d_in[1];
    const float* b1   = (const float*)d_in[2];
    const float* bn1g = (const float*)d_in[3];
    const float* bn1b = (const float*)d_in[4];
    const float* bn1m = (const float*)d_in[5];
    const float* bn1v = (const float*)d_in[6];
    const float* W2   = (const float*)d_in[7];
    const float* b2   = (const float*)d_in[8];
    const float* rbW  = (const float*)d_in[9];
    const float* rbb  = (const float*)d_in[10];
    const float* rbg  = (const float*)d_in[11];
    const float* rbbe = (const float*)d_in[12];
    const float* rbm  = (const float*)d_in[13];
    const float* rbv  = (const float*)d_in[14];
    const float* cb   = (const float*)d_in[15];
    const float* decW = (const float*)d_in[16];
    const float* decb = (const float*)d_in[17];
    float* out = (float*)d_out;

    __half *xh, *w1t, *wts, *cbh, *ha, *har, *hb, *gz;
    uint8_t *wq, *wqd, *q1, *q2;
    cudaGetSymbolAddress((void**)&xh,  g_xh);
    cudaGetSymbolAddress((void**)&w1t, g_w1t);
    cudaGetSymbolAddress((void**)&wts, g_wts);
    cudaGetSymbolAddress((void**)&wq,  g_wq);
    cudaGetSymbolAddress((void**)&wqd, g_wqd);
    cudaGetSymbolAddress((void**)&cbh, g_cbh);
    cudaGetSymbolAddress((void**)&ha,  g_ha);
    cudaGetSymbolAddress((void**)&har, g_har);
    cudaGetSymbolAddress((void**)&hb,  g_hb);
    cudaGetSymbolAddress((void**)&gz,  g_z);
    cudaGetSymbolAddress((void**)&q1,  g_q1);
    cudaGetSymbolAddress((void**)&q2,  g_q2);

    cudaFuncSetAttribute(gemm_h<EPI_BN_RELU, false>, cudaFuncAttributeMaxDynamicSharedMemorySize, SMEM_H16);
    cudaFuncSetAttribute(gemm_h<EPI_BIAS,    false>, cudaFuncAttributeMaxDynamicSharedMemorySize, SMEM_H16);
    cudaFuncSetAttribute(gemm_h<EPI_RES,     true >, cudaFuncAttributeMaxDynamicSharedMemorySize, SMEM_H16);
    cudaFuncSetAttribute(gemm_q<EPI_RES,  true,  true >, cudaFuncAttributeMaxDynamicSharedMemorySize, SMEM_Q);
    cudaFuncSetAttribute(gemm_q<EPI_RES,  false, false>, cudaFuncAttributeMaxDynamicSharedMemorySize, SMEM_Q);
    cudaFuncSetAttribute(gemm_q<EPI_SIG,  false, false>, cudaFuncAttributeMaxDynamicSharedMemorySize, SMEM_Q);
    cudaFuncSetAttribute(vq_h, cudaFuncAttributeMaxDynamicSharedMemorySize, VQ_SMEM);

    const size_t WS = (size_t)NEMB * NEMB;
    dim3 tb(32, 8);
    dim3 blk(256);
    dim3 gE(NEMB / 256, NB / 128);   // 4 x 32
    dim3 gD(NIN / 256,  NB / 128);   // 32 x 32

    // pre-pass
    cvt_x<<<(NB * NIN / 4 + 255) / 256, 256>>>(x, xh, NB * NIN / 4);
    transpose_f16<<<dim3(NEMB / 32, NIN / 32),  tb>>>(W1, w1t, NIN, NEMB);
    transpose_sq6<<<dim3(32, 32, 6), tb>>>(W2, rbW, wts, wq);
    transpose_q8<<<dim3(NIN / 32, NEMB / 32), tb>>>(decW, wqd, NEMB, NIN);

    __half* w2t = wts + 0 * WS;
    __half* wt0 = wts + 1 * WS;
    __half* wt1 = wts + 2 * WS;

    // encoder (all pure fp16 ldsm path)
    gemm_h<EPI_BN_RELU, false><<<gE, blk, SMEM_H16>>>(
        xh, w1t, b1, bn1g, bn1b, bn1m, bn1v, nullptr, ha, NB, NEMB, NIN);
    gemm_h<EPI_BIAS, false><<<gE, blk, SMEM_H16>>>(
        ha, w2t, b2, nullptr, nullptr, nullptr, nullptr, nullptr, hb, NB, NEMB, NEMB);
    gemm_h<EPI_RES, true><<<gE, blk, SMEM_H16>>>(
        hb, wt0, rbb + 0 * NEMB, rbg + 0 * NEMB, rbbe + 0 * NEMB,
        rbm + 0 * NEMB, rbv + 0 * NEMB, hb, har, NB, NEMB, NEMB);
    gemm_h<EPI_RES, true><<<gE, blk, SMEM_H16>>>(
        har, wt1, rbb + 1 * NEMB, rbg + 1 * NEMB, rbbe + 1 * NEMB,
        rbm + 1 * NEMB, rbv + 1 * NEMB, har, gz, NB, NEMB, NEMB);

    // vector quantizer (distances + argmin + fused gather/loss)
    prep_cb<<<NK / 8, 256>>>(cb, cbh);
    vq_h<<<NFLAT / 128, blk, VQ_SMEM>>>(gz, cbh, cb, hb, q1);
    finalize_kernel<<<1, 256>>>(out);

    // decoder (fp8 e4m3 mma, activations scaled by 4096)
    gemm_q<EPI_RES, true, true><<<gE, blk, SMEM_Q>>>(
        q1, wq + 0 * WS, rbb + 2 * NEMB, rbg + 2 * NEMB, rbbe + 2 * NEMB,
        rbm + 2 * NEMB, rbv + 2 * NEMB, hb, ha, q2, NB, NEMB, NEMB);
    gemm_q<EPI_RES, true, true><<<gE, blk, SMEM_Q>>>(
        q2, wq + 1 * WS, rbb + 3 * NEMB, rbg + 3 * NEMB, rbbe + 3 * NEMB,
        rbm + 3 * NEMB, rbv + 3 * NEMB, ha, hb, q1, NB, NEMB, NEMB);
    gemm_q<EPI_RES, false, false><<<gE, blk, SMEM_Q>>>(
        q1, wq + 2 * WS, rbb + 4 * NEMB, rbg + 4 * NEMB, rbbe + 4 * NEMB,
        rbm + 4 * NEMB, rbv + 4 * NEMB, hb, nullptr, q2, NB, NEMB, NEMB);
    gemm_q<EPI_SIG, false, false><<<gD, blk, SMEM_Q>>>(
        q2, wqd, decb, nullptr, nullptr, nullptr, nullptr, nullptr,
        out + 1, nullptr, NB, NIN, NEMB);
}

// round 16
// speedup vs baseline: 1.5141x; 1.0021x over previous
#include <cuda_runtime.h>
#include <cuda_fp16.h>
#include <cuda_fp8.h>
#include <math.h>
#include <stdint.h>

// ---------------- problem dims ----------------
#define NB    4096
#define NIN   8192
#define NEMB  1024
#define NK    4096
#define NCD   256
#define NFLAT 16384
#define OUT_PERP_OFF ((size_t)1 + (size_t)NB * (size_t)NIN)

#define EPI_BN_RELU 0
#define EPI_BIAS    1
#define EPI_RES     2
#define EPI_SIG     3

#define QSCALE     4096.0f
#define QSCALE_INV 0.000244140625f

// ---------------- scratch (device globals) ----------------
__device__ __half  g_xh [(size_t)NB * NIN];
__device__ __half  g_w1t[(size_t)NIN * NEMB];
__device__ __half  g_wts[(size_t)3 * NEMB * NEMB];    // W2, rb0, rb1 (fp16, [n][k])
__device__ uint8_t g_wq [(size_t)3 * NEMB * NEMB];    // rb2, rb3, rb4 (e4m3, [n][k])
__device__ uint8_t g_wqd[(size_t)NIN * NEMB];         // decW (e4m3, [n][k])
__device__ __half  g_cbh[(size_t)NK * NCD];
__device__ __half  g_ha [(size_t)NB * NEMB];
__device__ __half  g_har[(size_t)NB * NEMB];
__device__ __half  g_hb [(size_t)NB * NEMB];
__device__ __half  g_z  [(size_t)NB * NEMB];
__device__ uint8_t g_q1 [(size_t)NB * NEMB];
__device__ uint8_t g_q2 [(size_t)NB * NEMB];
__device__ float   g_cnorm[NK];
__device__ int     g_cnt[NK];
__device__ float   g_losspart[NFLAT / 128];

// ---------------- helpers ----------------
__device__ __forceinline__ void cp16(uint32_t dst, const void* src) {
    asm volatile("cp.async.cg.shared.global [%0], [%1], 16;" :: "r"(dst), "l"(src));
}
__device__ __forceinline__ void cp_commit() {
    asm volatile("cp.async.commit_group;");
}
template<int N>
__device__ __forceinline__ void cp_wait() {
    asm volatile("cp.async.wait_group %0;" :: "n"(N));
}
__device__ __forceinline__ void mma16(float* c, const uint32_t* a, const uint32_t* b) {
    asm volatile(
        "mma.sync.aligned.m16n8k16.row.col.f32.f16.f16.f32 "
        "{%0,%1,%2,%3},{%4,%5,%6,%7},{%8,%9},{%0,%1,%2,%3};"
        : "+f"(c[0]), "+f"(c[1]), "+f"(c[2]), "+f"(c[3])
        : "r"(a[0]), "r"(a[1]), "r"(a[2]), "r"(a[3]), "r"(b[0]), "r"(b[1]));
}
__device__ __forceinline__ void mmaq(float* c, const uint32_t* a, const uint32_t* b) {
    asm volatile(
        "mma.sync.aligned.m16n8k32.row.col.f32.e4m3.e4m3.f32 "
        "{%0,%1,%2,%3},{%4,%5,%6,%7},{%8,%9},{%0,%1,%2,%3};"
        : "+f"(c[0]), "+f"(c[1]), "+f"(c[2]), "+f"(c[3])
        : "r"(a[0]), "r"(a[1]), "r"(a[2]), "r"(a[3]), "r"(b[0]), "r"(b[1]));
}
__device__ __forceinline__ void ldsm4(uint32_t& r0, uint32_t& r1, uint32_t& r2, uint32_t& r3,
                                      uint32_t addr) {
    asm volatile("ldmatrix.sync.aligned.m8n8.x4.shared.b16 {%0,%1,%2,%3}, [%4];"
                 : "=r"(r0), "=r"(r1), "=r"(r2), "=r"(r3) : "r"(addr));
}
__device__ __forceinline__ uint16_t pack_q2(float lo, float hi) {
    uint16_t r;
    asm("cvt.rn.satfinite.e4m3x2.f32 %0, %1, %2;" : "=h"(r) : "f"(hi), "f"(lo));
    return r;
}
__device__ __forceinline__ uint32_t relu_h2(uint32_t v) {
    __half2 h = *(__half2*)&v;
    h = __hmax2(h, __float2half2_rn(0.f));
    return *(uint32_t*)&h;
}

// ================= fp16 tensor-core GEMM (256 thr, 3-stage, ldmatrix) =================
#define HBK   64
#define HA_STR 72
#define HAS   (128 * HA_STR)
#define HBS   (256 * HA_STR)
#define SMEM_H16 (3 * (HAS * 2 + HBS * 2))

template<int EPI, bool RELUA>
__global__ void __launch_bounds__(256, 1)
gemm_h(const __half* __restrict__ Ain, const __half* __restrict__ WT,
       const float* __restrict__ bias,
       const float* __restrict__ gamma, const float* __restrict__ beta,
       const float* __restrict__ mean,  const float* __restrict__ var,
       const __half* __restrict__ res,
       __half* __restrict__ out0,
       int M, int N, int K)
{
    extern __shared__ char smem[];
    const int ASTG = HAS * 2;
    const int BSTG = HBS * 2;
    __half* Bh = (__half*)(smem + 3 * ASTG);
    const uint32_t s_a = (uint32_t)__cvta_generic_to_shared(smem);
    const uint32_t s_b = (uint32_t)__cvta_generic_to_shared(Bh);

    const int tid  = threadIdx.x;
    const int lane = tid & 31;
    const int warp = tid >> 5;
    const int wm   = warp >> 2;
    const int wn   = warp & 3;
    const int row0 = blockIdx.y * 128;
    const int col0 = blockIdx.x * 256;
    const int l4   = lane >> 2;
    const int lm   = lane & 3;
    const int t8   = lane >> 3;
    const int jr   = lane & 7;

    uint32_t aBase[4], bBase[4];
#pragma unroll
    for (int mt = 0; mt < 4; mt++) {
        int r = wm * 64 + mt * 16 + ((t8 & 1) << 3) + jr;
        int c = (t8 >> 1) << 3;
        aBase[mt] = s_a + (uint32_t)(r * HA_STR + c) * 2;
    }
#pragma unroll
    for (int p = 0; p < 4; p++) {
        int r = wn * 64 + (2 * p + (t8 >> 1)) * 8 + jr;
        int c = (t8 & 1) << 3;
        bBase[p] = s_b + (uint32_t)(r * HA_STR + c) * 2;
    }

    float acc[4][8][4];
#pragma unroll
    for (int mt = 0; mt < 4; mt++)
#pragma unroll
        for (int nt = 0; nt < 8; nt++)
#pragma unroll
            for (int q = 0; q < 4; q++) acc[mt][nt][q] = 0.f;

    const int iters = K / HBK;

    auto loadA = [&](int s, int k0) {
#pragma unroll
        for (int i = 0; i < 4; i++) {
            int idx = i * 256 + tid;
            int r = idx >> 3, kc = (idx & 7) << 3;
            cp16(s_a + (uint32_t)(s * ASTG) + (uint32_t)(r * HA_STR + kc) * 2,
                 Ain + (size_t)(row0 + r) * K + k0 + kc);
        }
    };
    auto loadB = [&](int s, int k0) {
#pragma unroll
        for (int i = 0; i < 8; i++) {
            int idx = i * 256 + tid;
            int n = idx >> 3, kc = (idx & 7) << 3;
            cp16(s_b + (uint32_t)(s * BSTG) + (uint32_t)(n * HA_STR + kc) * 2,
                 WT + (size_t)(col0 + n) * K + k0 + kc);
        }
    };

    loadA(0, 0); loadB(0, 0); cp_commit();
    loadA(1, HBK); loadB(1, HBK); cp_commit();

    for (int it = 0; it < iters; it++) {
        if (it + 1 < iters) cp_wait<1>(); else cp_wait<0>();
        __syncthreads();
        if (it + 2 < iters) {
            int ps = (it + 2) % 3;
            loadA(ps, (it + 2) * HBK);
            loadB(ps, (it + 2) * HBK);
            cp_commit();
        }

        const int s = it % 3;
        const uint32_t aOff = (uint32_t)(s * ASTG);
        const uint32_t bOff = (uint32_t)(s * BSTG);
#pragma unroll
        for (int kk = 0; kk < HBK; kk += 16) {
            uint32_t af[4][4], bf[8][2];
#pragma unroll
            for (int mt = 0; mt < 4; mt++) {
                ldsm4(af[mt][0], af[mt][1], af[mt][2], af[mt][3],
                      aBase[mt] + aOff + (uint32_t)kk * 2);
                if (RELUA) {
#pragma unroll
                    for (int i = 0; i < 4; i++) af[mt][i] = relu_h2(af[mt][i]);
                }
            }
#pragma unroll
            for (int p = 0; p < 4; p++)
                ldsm4(bf[2 * p][0], bf[2 * p][1], bf[2 * p + 1][0], bf[2 * p + 1][1],
                      bBase[p] + bOff + (uint32_t)kk * 2);
#pragma unroll
            for (int mt = 0; mt < 4; mt++)
#pragma unroll
                for (int nt = 0; nt < 8; nt++)
                    mma16(acc[mt][nt], af[mt], bf[nt]);
        }
    }

    // ---- epilogue (single fp16 output) ----
#pragma unroll
    for (int nt = 0; nt < 8; nt++) {
        int c = col0 + wn * 64 + nt * 8 + (lm << 1);
        float b0 = bias[c], b1 = bias[c + 1];
        float g0 = 0.f, g1 = 0.f, be0 = 0.f, be1 = 0.f, m0 = 0.f, m1 = 0.f;
        if (EPI == EPI_BN_RELU || EPI == EPI_RES) {
            g0 = gamma[c]     * rsqrtf(var[c]     + 1e-5f);
            g1 = gamma[c + 1] * rsqrtf(var[c + 1] + 1e-5f);
            be0 = beta[c]; be1 = beta[c + 1];
            m0 = mean[c]; m1 = mean[c + 1];
        }
#pragma unroll
        for (int mt = 0; mt < 4; mt++) {
#pragma unroll
            for (int h = 0; h < 2; h++) {
                int r = row0 + wm * 64 + mt * 16 + l4 + h * 8;
                size_t off = (size_t)r * N + c;
                float x0 = acc[mt][nt][h * 2 + 0] + b0;
                float x1 = acc[mt][nt][h * 2 + 1] + b1;
                if (EPI == EPI_BN_RELU) {
                    x0 = fmaxf((x0 - m0) * g0 + be0, 0.f);
                    x1 = fmaxf((x1 - m1) * g1 + be1, 0.f);
                } else if (EPI == EPI_RES) {
                    __half2 rv = *(const __half2*)(res + off);
                    x0 = (x0 - m0) * g0 + be0 + __half2float(rv.x);
                    x1 = (x1 - m1) * g1 + be1 + __half2float(rv.y);
                }
                __half2 ov; ov.x = __float2half_rn(x0); ov.y = __float2half_rn(x1);
                *(__half2*)(out0 + off) = ov;
            }
        }
    }
}

// ================= fp8 e4m3 GEMM (decoder): 256 thr =================
#define QBK   128
#define QA_STR 144
#define QAS   (128 * QA_STR)
#define QBS   (256 * QA_STR)
#define SMEM_Q (3 * (QAS + QBS))

template<int EPI, bool QRELU, bool WH16>
__global__ void __launch_bounds__(256, 1)
gemm_q(const uint8_t* __restrict__ Ain, const uint8_t* __restrict__ WT,
       const float* __restrict__ bias,
       const float* __restrict__ gamma, const float* __restrict__ beta,
       const float* __restrict__ mean,  const float* __restrict__ var,
       const __half* __restrict__ res,
       void* __restrict__ out0, uint8_t* __restrict__ out1,
       int M, int N, int K)
{
    extern __shared__ char smem[];
    const uint32_t s_a = (uint32_t)__cvta_generic_to_shared(smem);
    const uint32_t s_b = s_a + 3 * QAS;

    const int tid  = threadIdx.x;
    const int lane = tid & 31;
    const int warp = tid >> 5;
    const int wm   = warp >> 2;
    const int wn   = warp & 3;
    const int row0 = blockIdx.y * 128;
    const int col0 = blockIdx.x * 256;
    const int l4   = lane >> 2;
    const int lm   = lane & 3;
    const int t8   = lane >> 3;
    const int jr   = lane & 7;

    uint32_t aBase[4], bBase[4];
#pragma unroll
    for (int mt = 0; mt < 4; mt++) {
        int r = wm * 64 + mt * 16 + ((t8 & 1) << 3) + jr;
        int cB = (t8 >> 1) << 4;
        aBase[mt] = s_a + (uint32_t)(r * QA_STR + cB);
    }
#pragma unroll
    for (int p = 0; p < 4; p++) {
        int r = wn * 64 + (2 * p + (t8 >> 1)) * 8 + jr;
        int cB = (t8 & 1) << 4;
        bBase[p] = s_b + (uint32_t)(r * QA_STR + cB);
    }

    float acc[4][8][4];
#pragma unroll
    for (int mt = 0; mt < 4; mt++)
#pragma unroll
        for (int nt = 0; nt < 8; nt++)
#pragma unroll
            for (int q = 0; q < 4; q++) acc[mt][nt][q] = 0.f;

    const int iters = K / QBK;

    auto loadA = [&](int s, int k0) {
#pragma unroll
        for (int i = 0; i < 4; i++) {
            int idx = i * 256 + tid;
            int r = idx >> 3, c16 = idx & 7;
            cp16(s_a + (uint32_t)(s * QAS) + (uint32_t)(r * QA_STR + c16 * 16),
                 Ain + (size_t)(row0 + r) * K + k0 + c16 * 16);
        }
    };
    auto loadB = [&](int s, int k0) {
#pragma unroll
        for (int i = 0; i < 8; i++) {
            int idx = i * 256 + tid;
            int n = idx >> 3, c16 = idx & 7;
            cp16(s_b + (uint32_t)(s * QBS) + (uint32_t)(n * QA_STR + c16 * 16),
                 WT + (size_t)(col0 + n) * K + k0 + c16 * 16);
        }
    };

    loadA(0, 0); loadB(0, 0); cp_commit();
    loadA(1, QBK); loadB(1, QBK); cp_commit();

    for (int it = 0; it < iters; it++) {
        if (it + 1 < iters) cp_wait<1>(); else cp_wait<0>();
        __syncthreads();
        if (it + 2 < iters) {
            int ps = (it + 2) % 3;
            loadA(ps, (it + 2) * QBK);
            loadB(ps, (it + 2) * QBK);
            cp_commit();
        }

        const int s = it % 3;
        const uint32_t aOff = (uint32_t)(s * QAS);
        const uint32_t bOff = (uint32_t)(s * QBS);
#pragma unroll
        for (int kk = 0; kk < QBK; kk += 32) {
            uint32_t af[4][4], bf[8][2];
#pragma unroll
            for (int mt = 0; mt < 4; mt++)
                ldsm4(af[mt][0], af[mt][1], af[mt][2], af[mt][3],
                      aBase[mt] + aOff + (uint32_t)kk);
#pragma unroll
            for (int p = 0; p < 4; p++)
                ldsm4(bf[2 * p][0], bf[2 * p][1], bf[2 * p + 1][0], bf[2 * p + 1][1],
                      bBase[p] + bOff + (uint32_t)kk);
#pragma unroll
            for (int mt = 0; mt < 4; mt++)
#pragma unroll
                for (int nt = 0; nt < 8; nt++)
                    mmaq(acc[mt][nt], af[mt], bf[nt]);
        }
    }

    // ---- epilogue ----
#pragma unroll
    for (int nt = 0; nt < 8; nt++) {
        int c = col0 + wn * 64 + nt * 8 + (lm << 1);
        float b0 = bias[c], b1 = bias[c + 1];
        float g0 = 0.f, g1 = 0.f, be0 = 0.f, be1 = 0.f, m0 = 0.f, m1 = 0.f;
        if (EPI == EPI_RES) {
            g0 = gamma[c]     * rsqrtf(var[c]     + 1e-5f);
            g1 = gamma[c + 1] * rsqrtf(var[c + 1] + 1e-5f);
            be0 = beta[c]; be1 = beta[c + 1];
            m0 = mean[c]; m1 = mean[c + 1];
        }
#pragma unroll
        for (int mt = 0; mt < 4; mt++) {
#pragma unroll
            for (int h = 0; h < 2; h++) {
                int r = row0 + wm * 64 + mt * 16 + l4 + h * 8;
                size_t off = (size_t)r * N + c;
                float x0 = acc[mt][nt][h * 2 + 0] * QSCALE_INV + b0;
                float x1 = acc[mt][nt][h * 2 + 1] * QSCALE_INV + b1;
                if (EPI == EPI_SIG) {
                    float* o = (float*)out0;
                    o[off]     = 1.f / (1.f + expf(-x0));
                    o[off + 1] = 1.f / (1.f + expf(-x1));
                    continue;
                }
                __half2 rv = *(const __half2*)(res + off);
                x0 = (x0 - m0) * g0 + be0 + __half2float(rv.x);
                x1 = (x1 - m1) * g1 + be1 + __half2float(rv.y);
                if (WH16) {
                    __half2 ov; ov.x = __float2half_rn(x0); ov.y = __float2half_rn(x1);
                    *(__half2*)((__half*)out0 + off) = ov;
                }
                float q0 = QRELU ? fmaxf(x0, 0.f) * QSCALE : x0 * QSCALE;
                float q1 = QRELU ? fmaxf(x1, 0.f) * QSCALE : x1 * QSCALE;
                *(uint16_t*)(out1 + off) = pack_q2(q0, q1);
            }
        }
    }
}

// ================= VQ: fp16 mma distances + argmin + fused gather/loss =================
#define AZ_STR 264
#define VQ_SMEM (128 * AZ_STR * 2 + 3 * HBS * 2)

__global__ void __launch_bounds__(256, 1)
vq_h(const __half* __restrict__ Z, const __half* __restrict__ CBH,
     const float* __restrict__ CB,
     __half* __restrict__ HQ, uint8_t* __restrict__ Q)
{
    extern __shared__ char smem[];
    __half* Az = (__half*)smem;
    __half* Bh = (__half*)(smem + 128 * AZ_STR * 2);
    const uint32_t s_az = (uint32_t)__cvta_generic_to_shared(Az);
    const uint32_t s_b  = (uint32_t)__cvta_generic_to_shared(Bh);
    __shared__ float sv[128][4];
    __shared__ int   si[128][4];
    __shared__ int   sidx[128];
    __shared__ float ws[8];

    const int tid  = threadIdx.x;
    const int lane = tid & 31;
    const int warp = tid >> 5;
    const int wm   = warp >> 2;
    const int wn   = warp & 3;
    const int row0 = blockIdx.x * 128;
    const int l4   = lane >> 2;
    const int lm   = lane & 3;
    const int t8   = lane >> 3;
    const int jr   = lane & 7;

    uint32_t aBase[4], bBase[4];
#pragma unroll
    for (int mt = 0; mt < 4; mt++) {
        int r = wm * 64 + mt * 16 + ((t8 & 1) << 3) + jr;
        int c = (t8 >> 1) << 3;
        aBase[mt] = s_az + (uint32_t)(r * AZ_STR + c) * 2;
    }
#pragma unroll
    for (int p = 0; p < 4; p++) {
        int r = wn * 64 + (2 * p + (t8 >> 1)) * 8 + jr;
        int c = (t8 & 1) << 3;
        bBase[p] = s_b + (uint32_t)(r * HA_STR + c) * 2;
    }

    auto loadB = [&](int s, int chunk) {
        int ct = chunk >> 2, k0 = (chunk & 3) * 64;
#pragma unroll
        for (int i = 0; i < 8; i++) {
            int idx = i * 256 + tid;
            int code = idx >> 3, kc = (idx & 7) << 3;
            cp16(s_b + (uint32_t)(s * (HBS * 2)) + (uint32_t)(code * HA_STR + kc) * 2,
                 CBH + (size_t)(ct * 256 + code) * NCD + k0 + kc);
        }
    };

#pragma unroll
    for (int i = 0; i < 16; i++) {
        int idx = i * 256 + tid;
        int r = idx >> 5, kc = (idx & 31) << 3;
        cp16(s_az + (uint32_t)(r * AZ_STR + kc) * 2,
             Z + (size_t)(row0 + r) * NCD + kc);
    }
    loadB(0, 0); cp_commit();
    loadB(1, 1); cp_commit();

    float minv[4][2];
    int   mini[4][2];
#pragma unroll
    for (int mt = 0; mt < 4; mt++)
#pragma unroll
        for (int h = 0; h < 2; h++) { minv[mt][h] = 3.4e38f; mini[mt][h] = 0; }

    float acc[4][8][4];
#pragma unroll
    for (int mt = 0; mt < 4; mt++)
#pragma unroll
        for (int nt = 0; nt < 8; nt++)
#pragma unroll
            for (int q = 0; q < 4; q++) acc[mt][nt][q] = 0.f;

    for (int c = 0; c < 64; c++) {
        if (c + 1 < 64) cp_wait<1>(); else cp_wait<0>();
        __syncthreads();
        if (c + 2 < 64) { loadB((c + 2) % 3, c + 2); cp_commit(); }

        const int s = c % 3;
        const uint32_t bOff = (uint32_t)(s * (HBS * 2));
        const int kg = (c & 3) * 64;
#pragma unroll
        for (int kk = 0; kk < 64; kk += 16) {
            uint32_t af[4][4], bf[8][2];
#pragma unroll
            for (int mt = 0; mt < 4; mt++)
                ldsm4(af[mt][0], af[mt][1], af[mt][2], af[mt][3],
                      aBase[mt] + (uint32_t)(kg + kk) * 2);
#pragma unroll
            for (int p = 0; p < 4; p++)
                ldsm4(bf[2 * p][0], bf[2 * p][1], bf[2 * p + 1][0], bf[2 * p + 1][1],
                      bBase[p] + bOff + (uint32_t)kk * 2);
#pragma unroll
            for (int mt = 0; mt < 4; mt++)
#pragma unroll
                for (int nt = 0; nt < 8; nt++)
                    mma16(acc[mt][nt], af[mt], bf[nt]);
        }

        if ((c & 3) == 3) {
            int ct = (c >> 2) * 256;
#pragma unroll
            for (int nt = 0; nt < 8; nt++) {
                int code = ct + wn * 64 + nt * 8 + (lm << 1);
                float cn0 = g_cnorm[code], cn1 = g_cnorm[code + 1];
#pragma unroll
                for (int mt = 0; mt < 4; mt++)
#pragma unroll
                    for (int h = 0; h < 2; h++) {
                        float d0 = cn0 - 2.f * acc[mt][nt][h * 2 + 0];
                        float d1 = cn1 - 2.f * acc[mt][nt][h * 2 + 1];
                        if (d0 < minv[mt][h]) { minv[mt][h] = d0; mini[mt][h] = code; }
                        if (d1 < minv[mt][h]) { minv[mt][h] = d1; mini[mt][h] = code + 1; }
                        acc[mt][nt][h * 2 + 0] = 0.f;
                        acc[mt][nt][h * 2 + 1] = 0.f;
                    }
            }
        }
    }

#pragma unroll
    for (int mt = 0; mt < 4; mt++)
#pragma unroll
        for (int h = 0; h < 2; h++) {
            float v = minv[mt][h]; int ix = mini[mt][h];
#pragma unroll
            for (int o = 1; o <= 2; o <<= 1) {
                float vo = __shfl_xor_sync(0xffffffffu, v, o);
                int   io = __shfl_xor_sync(0xffffffffu, ix, o);
                if (vo < v || (vo == v && io < ix)) { v = vo; ix = io; }
            }
            if (lm == 0) {
                int rl = wm * 64 + mt * 16 + l4 + h * 8;
                sv[rl][wn] = v; si[rl][wn] = ix;
            }
        }
    __syncthreads();
    if (tid < 128) {
        float bv = sv[tid][0]; int bi = si[tid][0];
#pragma unroll
        for (int t = 1; t < 4; t++) {
            float v = sv[tid][t]; int k2 = si[tid][t];
            if (v < bv || (v == bv && k2 < bi)) { bv = v; bi = k2; }
        }
        sidx[tid] = bi;
        atomicAdd(&g_cnt[bi], 1);
    }
    __syncthreads();

    // ---- fused gather + loss ----
    float s = 0.f;
#pragma unroll 4
    for (int i = 0; i < 16; i++) {
        int r = warp * 16 + i;
        int id = sidx[r];
        const float* q = CB + (size_t)id * NCD;
        __half*  o  = HQ + (size_t)(row0 + r) * NCD;
        uint8_t* oq = Q  + (size_t)(row0 + r) * NCD;
#pragma unroll
        for (int e = 0; e < 8; e++) {
            int d = e * 32 + lane;
            float qq = q[d];
            float zz = __half2float(Az[r * AZ_STR + d]);
            o[d]  = __float2half_rn(qq);
            oq[d] = (uint8_t)__nv_cvt_float_to_fp8(fmaxf(qq, 0.f) * QSCALE,
                                                   __NV_SATFINITE, __NV_E4M3);
            float t = qq - zz;
            s += t * t;
        }
    }
#pragma unroll
    for (int o = 16; o > 0; o >>= 1) s += __shfl_xor_sync(0xffffffffu, s, o);
    if (lane == 0) ws[warp] = s;
    __syncthreads();
    if (tid == 0) {
        float t = 0.f;
#pragma unroll
        for (int w = 0; w < 8; w++) t += ws[w];
        g_losspart[blockIdx.x] = t;
    }
}

// ---------------- pre-pass kernels ----------------
__global__ void cvt_x(const float* __restrict__ in, __half* __restrict__ out, int n4)
{
    int i = blockIdx.x * 256 + threadIdx.x;
    if (i < n4) {
        float4 v = ((const float4*)in)[i];
        ((__half2*)out)[2 * i]     = __floats2half2_rn(v.x, v.y);
        ((__half2*)out)[2 * i + 1] = __floats2half2_rn(v.z, v.w);
    }
}

__global__ __launch_bounds__(256)
void prep_cb(const float* __restrict__ CB, __half* __restrict__ CBH)
{
    int warp = threadIdx.x >> 5, lane = threadIdx.x & 31;
    int code = blockIdx.x * 8 + warp;
    const float* c = CB + (size_t)code * NCD;
    __half* ch = CBH + (size_t)code * NCD;
    float s = 0.f;
#pragma unroll
    for (int e = 0; e < 8; e++) {
        int d = e * 32 + lane;
        __half hv = __float2half_rn(c[d]);
        ch[d] = hv;
        float v = __half2float(hv);
        s += v * v;
    }
#pragma unroll
    for (int o = 16; o > 0; o >>= 1) s += __shfl_xor_sync(0xffffffffu, s, o);
    if (lane == 0) { g_cnorm[code] = s; g_cnt[code] = 0; }
}

// merged: z=0 -> W1 [NIN,NEMB] -> fp16 [NEMB][NIN]; z=1 -> decW [NEMB,NIN] -> e4m3 [NIN][NEMB]
__global__ void transpose_big2(const float* __restrict__ W1, const float* __restrict__ decW,
                               __half* __restrict__ W1T, uint8_t* __restrict__ DQT)
{
    __shared__ float t[32][33];
    int tx = threadIdx.x, ty = threadIdx.y;
    if (blockIdx.z == 0) {
        // transpose_f16(W1, w1t, K=NIN, N=NEMB): bx over NEMB/32, by over NIN/32
        int n0 = blockIdx.y * 32, k0 = blockIdx.x * 32;   // bx: 256 -> NIN blocks
#pragma unroll
        for (int i = 0; i < 32; i += 8)
            t[ty + i][tx] = W1[(size_t)(k0 + ty + i) * NEMB + n0 + tx];
        __syncthreads();
#pragma unroll
        for (int i = 0; i < 32; i += 8)
            W1T[(size_t)(n0 + ty + i) * NIN + k0 + tx] = __float2half_rn(t[tx][ty + i]);
    } else {
        // transpose_q8(decW, wqd, K=NEMB, N=NIN): n over NIN (bx: 256), k over NEMB (by: 32)
        int n0 = blockIdx.x * 32, k0 = blockIdx.y * 32;
#pragma unroll
        for (int i = 0; i < 32; i += 8)
            t[ty + i][tx] = decW[(size_t)(k0 + ty + i) * NIN + n0 + tx];
        __syncthreads();
#pragma unroll
        for (int i = 0; i < 32; i += 8)
            DQT[(size_t)(n0 + ty + i) * NEMB + k0 + tx] =
                (uint8_t)__nv_cvt_float_to_fp8(t[tx][ty + i], __NV_SATFINITE, __NV_E4M3);
    }
}

__global__ void transpose_sq6(const float* __restrict__ W2, const float* __restrict__ rbW,
                              __half* __restrict__ dh, uint8_t* __restrict__ dq)
{
    __shared__ float t[32][33];
    int z = blockIdx.z;
    const float* src = (z == 0) ? W2 : rbW + (size_t)(z - 1) * NEMB * NEMB;
    int n0 = blockIdx.x * 32, k0 = blockIdx.y * 32;
    int tx = threadIdx.x, ty = threadIdx.y;
#pragma unroll
    for (int i = 0; i < 32; i += 8)
        t[ty + i][tx] = src[(size_t)(k0 + ty + i) * NEMB + n0 + tx];
    __syncthreads();
    if (z < 3) {
        __half* out = dh + (size_t)z * NEMB * NEMB;
#pragma unroll
        for (int i = 0; i < 32; i += 8)
            out[(size_t)(n0 + ty + i) * NEMB + k0 + tx] = __float2half_rn(t[tx][ty + i]);
    } else {
        uint8_t* out = dq + (size_t)(z - 3) * NEMB * NEMB;
#pragma unroll
        for (int i = 0; i < 32; i += 8)
            out[(size_t)(n0 + ty + i) * NEMB + k0 + tx] =
                (uint8_t)__nv_cvt_float_to_fp8(t[tx][ty + i], __NV_SATFINITE, __NV_E4M3);
    }
}

__global__ __launch_bounds__(256)
void finalize_kernel(float* __restrict__ out)
{
    __shared__ float red[256];
    int tid = threadIdx.x;

    float s = (tid < NFLAT / 128) ? g_losspart[tid] : 0.f;
    red[tid] = s; __syncthreads();
    for (int o = 128; o > 0; o >>= 1) { if (tid < o) red[tid] += red[tid + o]; __syncthreads(); }
    float loss = red[0] * (1.25f / ((float)NB * (float)NEMB));
    __syncthreads();

    float e = 0.f;
    for (int i = tid; i < NK; i += 256) {
        float p = (float)g_cnt[i] * (1.0f / (float)NFLAT);
        e += p * logf(p + 1e-10f);
    }
    red[tid] = e; __syncthreads();
    for (int o = 128; o > 0; o >>= 1) { if (tid < o) red[tid] += red[tid + o]; __syncthreads(); }

    if (tid == 0) {
        out[0]            = loss;
        out[OUT_PERP_OFF] = expf(-red[0]);
    }
}

// ---------------- launch ----------------
extern "C" void kernel_launch(void* const* d_in, const int* in_sizes, int n_in,
                              void* d_out, int out_size)
{
    const float* x    = (const float*)d_in[0];
    const float* W1   = (const float*)d_in[1];
    const float* b1   = (const float*)d_in[2];
    const float* bn1g = (const float*)d_in[3];
    const float* bn1b = (const float*)d_in[4];
    const float* bn1m = (const float*)d_in[5];
    const float* bn1v = (const float*)d_in[6];
    const float* W2   = (const float*)d_in[7];
    const float* b2   = (const float*)d_in[8];
    const float* rbW  = (const float*)d_in[9];
    const float* rbb  = (const float*)d_in[10];
    const float* rbg  = (const float*)d_in[11];
    const float* rbbe = (const float*)d_in[12];
    const float* rbm  = (const float*)d_in[13];
    const float* rbv  = (const float*)d_in[14];
    const float* cb   = (const float*)d_in[15];
    const float* decW = (const float*)d_in[16];
    const float* decb = (const float*)d_in[17];
    float* out = (float*)d_out;

    __half *xh, *w1t, *wts, *cbh, *ha, *har, *hb, *gz;
    uint8_t *wq, *wqd, *q1, *q2;
    cudaGetSymbolAddress((void**)&xh,  g_xh);
    cudaGetSymbolAddress((void**)&w1t, g_w1t);
    cudaGetSymbolAddress((void**)&wts, g_wts);
    cudaGetSymbolAddress((void**)&wq,  g_wq);
    cudaGetSymbolAddress((void**)&wqd, g_wqd);
    cudaGetSymbolAddress((void**)&cbh, g_cbh);
    cudaGetSymbolAddress((void**)&ha,  g_ha);
    cudaGetSymbolAddress((void**)&har, g_har);
    cudaGetSymbolAddress((void**)&hb,  g_hb);
    cudaGetSymbolAddress((void**)&gz,  g_z);
    cudaGetSymbolAddress((void**)&q1,  g_q1);
    cudaGetSymbolAddress((void**)&q2,  g_q2);

    cudaFuncSetAttribute(gemm_h<EPI_BN_RELU, false>, cudaFuncAttributeMaxDynamicSharedMemorySize, SMEM_H16);
    cudaFuncSetAttribute(gemm_h<EPI_BIAS,    false>, cudaFuncAttributeMaxDynamicSharedMemorySize, SMEM_H16);
    cudaFuncSetAttribute(gemm_h<EPI_RES,     true >, cudaFuncAttributeMaxDynamicSharedMemorySize, SMEM_H16);
    cudaFuncSetAttribute(gemm_q<EPI_RES,  true,  true >, cudaFuncAttributeMaxDynamicSharedMemorySize, SMEM_Q);
    cudaFuncSetAttribute(gemm_q<EPI_RES,  false, false>, cudaFuncAttributeMaxDynamicSharedMemorySize, SMEM_Q);
    cudaFuncSetAttribute(gemm_q<EPI_SIG,  false, false>, cudaFuncAttributeMaxDynamicSharedMemorySize, SMEM_Q);
    cudaFuncSetAttribute(vq_h, cudaFuncAttributeMaxDynamicSharedMemorySize, VQ_SMEM);

    const size_t WS = (size_t)NEMB * NEMB;
    dim3 tb(32, 8);
    dim3 blk(256);
    dim3 gE(NEMB / 256, NB / 128);   // 4 x 32
    dim3 gD(NIN / 256,  NB / 128);   // 32 x 32

    // pre-pass (3 launches)
    cvt_x<<<(NB * NIN / 4 + 255) / 256, 256>>>(x, xh, NB * NIN / 4);
    transpose_big2<<<dim3(NIN / 32, NEMB / 32, 2), tb>>>(W1, decW, w1t, wqd);
    transpose_sq6<<<dim3(32, 32, 6), tb>>>(W2, rbW, wts, wq);

    __half* w2t = wts + 0 * WS;
    __half* wt0 = wts + 1 * WS;
    __half* wt1 = wts + 2 * WS;

    // encoder (all pure fp16 ldsm path)
    gemm_h<EPI_BN_RELU, false><<<gE, blk, SMEM_H16>>>(
        xh, w1t, b1, bn1g, bn1b, bn1m, bn1v, nullptr, ha, NB, NEMB, NIN);
    gemm_h<EPI_BIAS, false><<<gE, blk, SMEM_H16>>>(
        ha, w2t, b2, nullptr, nullptr, nullptr, nullptr, nullptr, hb, NB, NEMB, NEMB);
    gemm_h<EPI_RES, true><<<gE, blk, SMEM_H16>>>(
        hb, wt0, rbb + 0 * NEMB, rbg + 0 * NEMB, rbbe + 0 * NEMB,
        rbm + 0 * NEMB, rbv + 0 * NEMB, hb, har, NB, NEMB, NEMB);
    gemm_h<EPI_RES, true><<<gE, blk, SMEM_H16>>>(
        har, wt1, rbb + 1 * NEMB, rbg + 1 * NEMB, rbbe + 1 * NEMB,
        rbm + 1 * NEMB, rbv + 1 * NEMB, har, gz, NB, NEMB, NEMB);

    // vector quantizer (distances + argmin + fused gather/loss)
    prep_cb<<<NK / 8, 256>>>(cb, cbh);
    vq_h<<<NFLAT / 128, blk, VQ_SMEM>>>(gz, cbh, cb, hb, q1);
    finalize_kernel<<<1, 256>>>(out);

    // decoder (fp8 e4m3 mma, activations scaled by 4096)
    gemm_q<EPI_RES, true, true><<<gE, blk, SMEM_Q>>>(
        q1, wq + 0 * WS, rbb + 2 * NEMB, rbg + 2 * NEMB, rbbe + 2 * NEMB,
        rbm + 2 * NEMB, rbv + 2 * NEMB, hb, ha, q2, NB, NEMB, NEMB);
    gemm_q<EPI_RES, true, true><<<gE, blk, SMEM_Q>>>(
        q2, wq + 1 * WS, rbb + 3 * NEMB, rbg + 3 * NEMB, rbbe + 3 * NEMB,
        rbm + 3 * NEMB, rbv + 3 * NEMB, ha, hb, q1, NB, NEMB, NEMB);
    gemm_q<EPI_RES, false, false><<<gE, blk, SMEM_Q>>>(
        q1, wq + 2 * WS, rbb + 4 * NEMB, rbg + 4 * NEMB, rbbe + 4 * NEMB,
        rbm + 4 * NEMB, rbv + 4 * NEMB, hb, nullptr, q2, NB, NEMB, NEMB);
    gemm_q<EPI_SIG, false, false><<<gD, blk, SMEM_Q>>>(
        q2, wqd, decb, nullptr, nullptr, nullptr, nullptr, nullptr,
        out + 1, nullptr, NB, NIN, NEMB);
}